// round 4
// baseline (speedup 1.0000x reference)
#include <cuda_runtime.h>
#include <math.h>

#define NB 8
#define NL 512
#define NE 128
#define NT1 129
#define NT2 513
#define M1R (NB*NT1)        // 1032
#define M2R (NB*NT2)        // 4104
#define MTR (M1R+M2R)       // 5136

// ---------------- device scratch ----------------
__device__ float g_key_e[NB*NL*NE];
__device__ float g_clsq [128*NE];
__device__ float g_Qb   [NB*NL*NE];
__device__ float g_Kb   [NB*NL*NE];
__device__ float g_Qc   [128*NE];
__device__ float g_o32a [NB*NL*32];
__device__ float g_o32c [NB*128*32];
__device__ float g_X    [MTR*128];   // merged tblock input (h rows then h2 rows)
__device__ float g_Q    [MTR*128];
__device__ float g_K    [MTR*128];
__device__ float g_V    [MTR*128];
__device__ float g_AO   [MTR*128];
__device__ float g_X2   [MTR*128];   // post-LN1
__device__ float g_F    [MTR*128];   // relu(ffn1)
__device__ float g_hout [M1R*128];

// ---------------- time embedding ----------------
__global__ void emb_kernel(const float* __restrict__ ts,
                           const float* __restrict__ w_per, const float* __restrict__ b_per,
                           const float* __restrict__ w_lin, const float* __restrict__ b_lin)
{
    int row = blockIdx.x, j = threadIdx.x;
    float t; float* dst;
    if (row < NB*NL) { t = ts[row]; dst = g_key_e + (size_t)row*NE; }
    else             { int i = row - NB*NL; t = (float)i * (1.0f/127.0f); dst = g_clsq + (size_t)i*NE; }
    float v;
    if (j == 0) v = t*w_lin[0] + b_lin[0];
    else        v = sinf(t*w_per[j-1] + b_per[j-1]);
    dst[j] = v;
}

// ---------------- 64x64-tile SGEMM body (K=N=128) ----------------
__device__ __forceinline__ void gemm64x64(const float* __restrict__ A, const float* __restrict__ W,
                                          const float* __restrict__ bias, float* __restrict__ C,
                                          int M, int relu)
{
    __shared__ float As[16][64];
    __shared__ float Ws[16][64];
    const int tid = threadIdx.x;            // 256 threads
    const int tn = tid & 15, tm = tid >> 4;
    const int m0 = blockIdx.x * 64, n0 = blockIdx.y * 64;
    float acc[4][4];
    #pragma unroll
    for (int i=0;i<4;i++)
        #pragma unroll
        for (int j=0;j<4;j++) acc[i][j] = 0.f;

    const int la  = tid * 4;
    const int lar = la >> 4, lac = la & 15;   // A tile: 64 rows x 16 cols
    const int lwr = la >> 6, lwc = la & 63;   // W tile: 16 rows x 64 cols

    for (int kk = 0; kk < 128; kk += 16) {
        float4 av = make_float4(0.f,0.f,0.f,0.f);
        int gm = m0 + lar;
        if (gm < M) av = *(const float4*)(A + (size_t)gm*128 + kk + lac);
        float4 wv = *(const float4*)(W + (size_t)(kk+lwr)*128 + n0 + lwc);
        __syncthreads();
        As[lac+0][lar]=av.x; As[lac+1][lar]=av.y; As[lac+2][lar]=av.z; As[lac+3][lar]=av.w;
        *(float4*)&Ws[lwr][lwc] = wv;
        __syncthreads();
        #pragma unroll
        for (int k=0;k<16;k++) {
            float a[4], b[4];
            *(float4*)a = *(const float4*)&As[k][tm*4];
            *(float4*)b = *(const float4*)&Ws[k][tn*4];
            #pragma unroll
            for (int i=0;i<4;i++)
                #pragma unroll
                for (int j=0;j<4;j++) acc[i][j] = fmaf(a[i], b[j], acc[i][j]);
        }
    }
    float4 bv4 = *(const float4*)(bias + n0 + tn*4);
    float bb[4] = {bv4.x, bv4.y, bv4.z, bv4.w};
    #pragma unroll
    for (int i=0;i<4;i++) {
        int gm = m0 + tm*4 + i;
        if (gm < M) {
            float4 o;
            o.x = acc[i][0]+bb[0]; o.y = acc[i][1]+bb[1];
            o.z = acc[i][2]+bb[2]; o.w = acc[i][3]+bb[3];
            if (relu) { o.x=fmaxf(o.x,0.f); o.y=fmaxf(o.y,0.f); o.z=fmaxf(o.z,0.f); o.w=fmaxf(o.w,0.f); }
            *(float4*)(C + (size_t)gm*128 + n0 + tn*4) = o;
        }
    }
}

// K/Q projections of embeddings (z=0: Kb, z=1: Qb, z=2: Qc)
__global__ void kq_gemm_kernel(const float* __restrict__ Wq, const float* __restrict__ bq,
                               const float* __restrict__ Wk, const float* __restrict__ bk)
{
    const float *A, *W, *bias; float* C; int M;
    if (blockIdx.z == 0)      { A=g_key_e; W=Wk; bias=bk; C=g_Kb; M=NB*NL; }
    else if (blockIdx.z == 1) { A=g_key_e; W=Wq; bias=bq; C=g_Qb; M=NB*NL; }
    else                      { A=g_clsq;  W=Wq; bias=bq; C=g_Qc; M=128;  }
    if (blockIdx.x*64 >= M) return;
    gemm64x64(A, W, bias, C, M, 0);
}

// QKV for merged tblock rows (z selects q/k/v)
__global__ void qkv_gemm_kernel(const float* __restrict__ Wq, const float* __restrict__ bq,
                                const float* __restrict__ Wk, const float* __restrict__ bk,
                                const float* __restrict__ Wv, const float* __restrict__ bv)
{
    const float *W, *bias; float* C;
    if (blockIdx.z == 0)      { W=Wq; bias=bq; C=g_Q; }
    else if (blockIdx.z == 1) { W=Wk; bias=bk; C=g_K; }
    else                      { W=Wv; bias=bv; C=g_V; }
    gemm64x64(g_X, W, bias, C, MTR, 0);
}

// plain gemm (used for ffn1 with relu)
__global__ void gemm_kernel(const float* __restrict__ A, const float* __restrict__ W,
                            const float* __restrict__ bias, float* __restrict__ C,
                            int M, int relu)
{
    gemm64x64(A, W, bias, C, M, relu);
}

// ---------------- GEMM (32x128 tile) + bias + residual + LayerNorm ----------------
__global__ void gemm_ln_kernel(const float* __restrict__ A, const float* __restrict__ W,
                               const float* __restrict__ bias, const float* __restrict__ Res,
                               const float* __restrict__ lng, const float* __restrict__ lnb,
                               float* __restrict__ out, float* __restrict__ dlast,
                               float* __restrict__ hout, int mode)
{
    __shared__ float As[16][32];
    __shared__ float Ws[16][128];
    const int tid = threadIdx.x;          // 256 threads
    const int tn = tid & 31, tm = tid >> 5;
    const int m0 = blockIdx.x * 32;
    float acc[4][4];
    #pragma unroll
    for (int i=0;i<4;i++)
        #pragma unroll
        for (int j=0;j<4;j++) acc[i][j] = 0.f;

    const int lam = tid & 31, lak = (tid >> 5) * 2;   // A: 32 rows x 16 k (float2/thread)

    for (int kk = 0; kk < 128; kk += 16) {
        float2 av = make_float2(0.f,0.f);
        int gm = m0 + lam;
        if (gm < MTR) av = *(const float2*)(A + (size_t)gm*128 + kk + lak);
        float4 wv0, wv1;
        {
            int i0 = tid*4;
            wv0 = *(const float4*)(W + (size_t)(kk + (i0>>7))*128 + (i0&127));
            int i1 = tid*4 + 1024;
            wv1 = *(const float4*)(W + (size_t)(kk + (i1>>7))*128 + (i1&127));
        }
        __syncthreads();
        As[lak][lam] = av.x; As[lak+1][lam] = av.y;
        { int i0 = tid*4;        *(float4*)&Ws[i0>>7][i0&127] = wv0; }
        { int i1 = tid*4 + 1024; *(float4*)&Ws[i1>>7][i1&127] = wv1; }
        __syncthreads();
        #pragma unroll
        for (int k=0;k<16;k++) {
            float a[4], b[4];
            *(float4*)a = *(const float4*)&As[k][tm*4];
            *(float4*)b = *(const float4*)&Ws[k][tn*4];
            #pragma unroll
            for (int i=0;i<4;i++)
                #pragma unroll
                for (int j=0;j<4;j++) acc[i][j] = fmaf(a[i], b[j], acc[i][j]);
        }
    }

    float4 bb4 = *(const float4*)(bias + tn*4);
    float bb[4] = {bb4.x, bb4.y, bb4.z, bb4.w};
    float4 g4 = *(const float4*)(lng + tn*4);
    float4 be4 = *(const float4*)(lnb + tn*4);
    float gg[4] = {g4.x, g4.y, g4.z, g4.w};
    float lb[4] = {be4.x, be4.y, be4.z, be4.w};

    #pragma unroll
    for (int i=0;i<4;i++) {
        int r = m0 + tm*4 + i;
        if (r >= MTR) continue;
        float4 rv = *(const float4*)(Res + (size_t)r*128 + tn*4);
        float v[4];
        v[0] = acc[i][0] + bb[0] + rv.x;
        v[1] = acc[i][1] + bb[1] + rv.y;
        v[2] = acc[i][2] + bb[2] + rv.z;
        v[3] = acc[i][3] + bb[3] + rv.w;
        float s = v[0]+v[1]+v[2]+v[3];
        float s2 = v[0]*v[0]+v[1]*v[1]+v[2]*v[2]+v[3]*v[3];
        #pragma unroll
        for (int off=16; off>0; off>>=1) {
            s  += __shfl_xor_sync(0xffffffffu, s,  off);
            s2 += __shfl_xor_sync(0xffffffffu, s2, off);
        }
        float mean = s * (1.f/128.f);
        float var  = s2 * (1.f/128.f) - mean*mean;
        float rs   = rsqrtf(var + 1e-5f);
        float4 o;
        o.x = (v[0]-mean)*rs*gg[0] + lb[0];
        o.y = (v[1]-mean)*rs*gg[1] + lb[1];
        o.z = (v[2]-mean)*rs*gg[2] + lb[2];
        o.w = (v[3]-mean)*rs*gg[3] + lb[3];
        if (mode == 0) {
            *(float4*)(out + (size_t)r*128 + tn*4) = o;
        } else {
            if (r < M1R) {
                *(float4*)(hout + (size_t)r*128 + tn*4) = o;
            } else {
                int rr = r - M1R;
                int t  = rr % NT2;
                if (t == 0) continue;
                int b  = rr / NT2;
                *(float4*)(dlast + ((size_t)b*NL + t - 1)*128 + tn*4) = o;
            }
        }
    }
}

// ---------------- masked per-channel attention (mTA), 4 threads/query ----------------
// 256 threads: 64 queries x (2 key-halves x 2 dim-halves)
__global__ void mta_kernel(const float* __restrict__ Qmain, const float* __restrict__ Qcls,
                           const float* __restrict__ K, const float* __restrict__ X,
                           float* __restrict__ o32main, float* __restrict__ o32cls)
{
    const int bh = blockIdx.y, b = bh >> 1, h = bh & 1;
    const bool cls = blockIdx.x >= 8;
    const int tile = cls ? (blockIdx.x - 8) : blockIdx.x;
    const float* Q = cls ? Qcls : Qmain;
    const int qStride = cls ? 0 : NL*128;
    const int Lq = cls ? 128 : NL;
    float* o32 = cls ? o32cls : o32main;

    const int tid = threadIdx.x, lane = tid & 31, warp = tid >> 5;
    const int qsub = lane & 7;
    const int dh = (lane >> 3) & 1;
    const int kh = lane >> 4;
    const int qi = tile*64 + warp*8 + qsub;

    __shared__ float sK[2][32][64];
    __shared__ float sX[2][32][16];

    float4 qreg[8];
    const float* qp = Q + (size_t)b*qStride + (size_t)qi*128 + h*64 + dh*32;
    #pragma unroll
    for (int i=0;i<8;i++) qreg[i] = *(const float4*)(qp + i*4);

    float m = -1e30f;
    float den[8], num[8];
    #pragma unroll
    for (int c=0;c<8;c++){ den[c]=0.f; num[c]=0.f; }

    for (int c=0;c<8;c++) {             // 8 chunks of 32 keys per half
        __syncthreads();
        #pragma unroll
        for (int u=0;u<4;u++) {
            int e = (tid*4+u)*4;                // 0..4092 (4096 floats total)
            int hh = e>>11, kk = (e>>6)&31, d = e&63;
            int kglob = hh*256 + c*32 + kk;
            *(float4*)&sK[hh][kk][d] =
                *(const float4*)(K + ((size_t)b*NL + kglob)*128 + h*64 + d);
        }
        {
            int e = tid*4;                      // 0..1020 (1024 floats total)
            int hh = e>>9, kk = (e>>4)&31, d = e&15;
            int kglob = hh*256 + c*32 + kk;
            *(float4*)&sX[hh][kk][d] =
                *(const float4*)(X + ((size_t)b*NL + kglob)*16 + d);
        }
        __syncthreads();
        for (int kk=0;kk<32;kk++) {
            const float4* kr = (const float4*)&sK[kh][kk][dh*32];
            float4 a4 = make_float4(0.f,0.f,0.f,0.f);
            #pragma unroll
            for (int i=0;i<8;i++) {
                float4 kv = kr[i];
                a4.x = fmaf(kv.x, qreg[i].x, a4.x);
                a4.y = fmaf(kv.y, qreg[i].y, a4.y);
                a4.z = fmaf(kv.z, qreg[i].z, a4.z);
                a4.w = fmaf(kv.w, qreg[i].w, a4.w);
            }
            float s = (a4.x+a4.y)+(a4.z+a4.w);
            s += __shfl_xor_sync(0xffffffffu, s, 8);
            s *= 0.125f;
            if (s > m) {
                float f = __expf(m - s);
                #pragma unroll
                for (int cc=0;cc<8;cc++){ den[cc]*=f; num[cc]*=f; }
                m = s;
            }
            float e = __expf(s - m);
            const float* xr = sX[kh][kk];
            #pragma unroll
            for (int cc=0;cc<8;cc++) {
                float t = e * xr[8+cc];
                den[cc] += t;
                num[cc] = fmaf(t, xr[cc], num[cc]);
            }
        }
    }
    float m2 = __shfl_xor_sync(0xffffffffu, m, 16);
    float Mx = fmaxf(m, m2);
    float f1 = __expf(m - Mx), f2 = __expf(m2 - Mx);
    #pragma unroll
    for (int cc=0;cc<8;cc++) {
        float d2 = __shfl_xor_sync(0xffffffffu, den[cc], 16);
        float n2 = __shfl_xor_sync(0xffffffffu, num[cc], 16);
        den[cc] = den[cc]*f1 + d2*f2;
        num[cc] = num[cc]*f1 + n2*f2;
    }
    if (kh == 0 && dh == 0) {
        float res[16];
        #pragma unroll
        for (int cc=0;cc<8;cc++) {
            bool ok = den[cc] > 0.f;
            res[cc]   = ok ? num[cc]/den[cc] : 0.f;
            res[8+cc] = ok ? 1.f : 0.f;
        }
        float* dst = o32 + ((size_t)b*Lq + qi)*32 + h*16;
        #pragma unroll
        for (int i=0;i<4;i++)
            *(float4*)(dst + i*4) = make_float4(res[i*4],res[i*4+1],res[i*4+2],res[i*4+3]);
    }
}

// ---------------- 32->128 projection into merged X + cls-row fill ----------------
__global__ void proj32_kernel(const float* __restrict__ Am, const float* __restrict__ Ac,
                              const float* __restrict__ W, const float* __restrict__ bias,
                              const float* __restrict__ pos, const float* __restrict__ cls_emb)
{
    if (blockIdx.x == 160) {     // cls token rows for both parts
        for (int i = threadIdx.x; i < 1024; i += 256) {
            int b = i >> 7, j = i & 127;
            float cv = cls_emb[j];
            g_X[((size_t)b*NT1)*128 + j] = cv;
            g_X[((size_t)M1R + (size_t)b*NT2)*128 + j] = cv + pos[j];
        }
        return;
    }
    __shared__ float sW[32*128];
    __shared__ float sA[32*32];
    const bool cls = blockIdx.x >= 128;
    const float* A = cls ? Ac : Am;
    const int Lq = cls ? 128 : NL;
    const int r0 = (cls ? (blockIdx.x - 128) : blockIdx.x) * 32;
    for (int i = threadIdx.x; i < 4096; i += 256) sW[i] = W[i];
    for (int i = threadIdx.x; i < 1024; i += 256)
        sA[i] = A[(size_t)(r0 + (i >> 5))*32 + (i & 31)];
    __syncthreads();
    #pragma unroll
    for (int u=0;u<16;u++) {
        int oi = threadIdx.x + u*256;
        int lr = oi >> 7, col = oi & 127;
        int r = r0 + lr;
        float acc = bias[col];
        #pragma unroll
        for (int k=0;k<32;k++) acc = fmaf(sA[lr*32+k], sW[k*128+col], acc);
        int bb = r / Lq, q = r % Lq;
        size_t row;
        if (cls) row = (size_t)bb*NT1 + 1 + q;
        else   { row = (size_t)M1R + (size_t)bb*NT2 + 1 + q; acc += pos[(size_t)(1+q)*128 + col]; }
        g_X[row*128 + col] = acc;
    }
}

// ---------------- transformer-block attention, 4 threads/query ----------------
// 256 threads: 64 queries x (2 key-halves x 2 dim-halves)
__global__ void tattn_kernel()
{
    const int y = blockIdx.y;
    const int part = y >> 4;              // 0: T1 block, 1: T2 block
    const int bh = y & 15, b = bh >> 1, h = bh & 1;
    const int T = part ? NT2 : NT1;
    const int base = part ? (M1R + b*NT2) : (b*NT1);
    if (blockIdx.x * 64 >= T) return;

    const int tid = threadIdx.x, lane = tid & 31, warp = tid >> 5;
    const int qsub = lane & 7;
    const int dh = (lane >> 3) & 1;
    const int kh = lane >> 4;
    const int qi = blockIdx.x*64 + warp*8 + qsub;

    __shared__ float sK[2][32][64];
    __shared__ float sV[2][32][64];

    float4 qreg[8];
    if (qi < T) {
        const float* qp = g_Q + ((size_t)base + qi)*128 + h*64 + dh*32;
        #pragma unroll
        for (int i=0;i<8;i++) qreg[i] = *(const float4*)(qp + i*4);
    } else {
        #pragma unroll
        for (int i=0;i<8;i++) qreg[i] = make_float4(0.f,0.f,0.f,0.f);
    }
    float m = -1e30f, l = 0.f;
    float o[32];
    #pragma unroll
    for (int d=0;d<32;d++) o[d]=0.f;

    const int half0 = (T + 1) >> 1;
    const int kbase = kh ? half0 : 0;
    const int kend  = kh ? T : half0;
    const int hl1 = T - half0;
    const int nch = (((half0 > hl1) ? half0 : hl1) + 31) >> 5;

    for (int c=0;c<nch;c++) {
        __syncthreads();
        #pragma unroll
        for (int u=0;u<8;u++) {
            int e = (tid*8 + u)*4;            // 0..8188 (8192 floats K+V)
            int isV = e >> 12;
            int e2 = e & 4095;
            int hh = e2 >> 11, kk = (e2 >> 6) & 31, d = e2 & 63;
            int kglob = (hh ? half0 : 0) + c*32 + kk;
            int lim = hh ? T : half0;
            float4 v = make_float4(0.f,0.f,0.f,0.f);
            if (kglob < lim) {
                const float* src = (isV ? g_V : g_K) + ((size_t)base + kglob)*128 + h*64 + d;
                v = *(const float4*)src;
            }
            float* dst = isV ? &sV[hh][kk][d] : &sK[hh][kk][d];
            *(float4*)dst = v;
        }
        __syncthreads();
        const int k0 = kbase + c*32;
        for (int kk=0;kk<32;kk++) {
            const float4* kr = (const float4*)&sK[kh][kk][dh*32];
            float4 a4 = make_float4(0.f,0.f,0.f,0.f);
            #pragma unroll
            for (int i=0;i<8;i++) {
                float4 kv = kr[i];
                a4.x = fmaf(kv.x, qreg[i].x, a4.x);
                a4.y = fmaf(kv.y, qreg[i].y, a4.y);
                a4.z = fmaf(kv.z, qreg[i].z, a4.z);
                a4.w = fmaf(kv.w, qreg[i].w, a4.w);
            }
            float s = (a4.x+a4.y)+(a4.z+a4.w);
            s += __shfl_xor_sync(0xffffffffu, s, 8);
            s *= 0.125f;
            if (k0 + kk < kend) {
                if (s > m) {
                    float f = __expf(m - s);
                    l *= f;
                    #pragma unroll
                    for (int d=0;d<32;d++) o[d]*=f;
                    m = s;
                }
                float e = __expf(s - m);
                l += e;
                const float4* vr = (const float4*)&sV[kh][kk][dh*32];
                #pragma unroll
                for (int i=0;i<8;i++) {
                    float4 vv = vr[i];
                    o[i*4+0] = fmaf(e, vv.x, o[i*4+0]);
                    o[i*4+1] = fmaf(e, vv.y, o[i*4+1]);
                    o[i*4+2] = fmaf(e, vv.z, o[i*4+2]);
                    o[i*4+3] = fmaf(e, vv.w, o[i*4+3]);
                }
            }
        }
    }
    // merge the two key-halves (partner = lane ^ 16)
    float m2 = __shfl_xor_sync(0xffffffffu, m, 16);
    float Mx = fmaxf(m, m2);
    float f1 = __expf(m - Mx), f2 = __expf(m2 - Mx);
    float l2 = __shfl_xor_sync(0xffffffffu, l, 16);
    l = l*f1 + l2*f2;
    #pragma unroll
    for (int d=0;d<32;d++) {
        float o2 = __shfl_xor_sync(0xffffffffu, o[d], 16);
        o[d] = o[d]*f1 + o2*f2;
    }
    if (kh == 0 && qi < T) {
        float inv = 1.0f / l;
        float* dst = g_AO + ((size_t)base + qi)*128 + h*64 + dh*32;
        #pragma unroll
        for (int i=0;i<8;i++)
            *(float4*)(dst + i*4) = make_float4(o[i*4]*inv, o[i*4+1]*inv, o[i*4+2]*inv, o[i*4+3]*inv);
    }
}

// ---------------- cls pooling ----------------
__global__ void pool_kernel(const float* __restrict__ pW,
                            const float* __restrict__ pb, float* __restrict__ dout)
{
    int b = blockIdx.x, j = threadIdx.x;
    __shared__ float s[128];
    s[j] = g_hout[((size_t)b*NT1)*128 + j];
    __syncthreads();
    float acc = pb[j];
    #pragma unroll
    for (int k=0;k<128;k++) acc = fmaf(s[k], pW[k*128 + j], acc);
    dout[b*128 + j] = tanhf(acc);
}

// ---------------- launch ----------------
extern "C" void kernel_launch(void* const* d_in, const int* in_sizes, int n_in,
                              void* d_out, int out_size)
{
    (void)in_sizes; (void)n_in; (void)out_size;
    const float* x       = (const float*)d_in[0];
    const float* ts      = (const float*)d_in[1];
    const float* w_per   = (const float*)d_in[2];
    const float* b_per   = (const float*)d_in[3];
    const float* w_lin   = (const float*)d_in[4];
    const float* b_lin   = (const float*)d_in[5];
    const float* Wq_t    = (const float*)d_in[6];
    const float* bq_t    = (const float*)d_in[7];
    const float* Wk_t    = (const float*)d_in[8];
    const float* bk_t    = (const float*)d_in[9];
    const float* Wo_t    = (const float*)d_in[10];
    const float* bo_t    = (const float*)d_in[11];
    const float* pos_emb = (const float*)d_in[12];
    const float* cls_emb = (const float*)d_in[13];
    const float* tWq = (const float*)d_in[14];
    const float* tbq = (const float*)d_in[15];
    const float* tWk = (const float*)d_in[16];
    const float* tbk = (const float*)d_in[17];
    const float* tWv = (const float*)d_in[18];
    const float* tbv = (const float*)d_in[19];
    const float* tWo = (const float*)d_in[20];
    const float* tbo = (const float*)d_in[21];
    const float* ln1_g = (const float*)d_in[22];
    const float* ln1_b = (const float*)d_in[23];
    const float* fW1 = (const float*)d_in[24];
    const float* fb1 = (const float*)d_in[25];
    const float* fW2 = (const float*)d_in[26];
    const float* fb2 = (const float*)d_in[27];
    const float* ln2_g = (const float*)d_in[28];
    const float* ln2_b = (const float*)d_in[29];
    const float* pW  = (const float*)d_in[30];
    const float* pb  = (const float*)d_in[31];
    float* dout = (float*)d_out;

    float *Qb, *Kb, *Qc, *o32a, *o32c, *X2, *AO, *F, *hout;
    cudaGetSymbolAddress((void**)&Qb,   g_Qb);
    cudaGetSymbolAddress((void**)&Kb,   g_Kb);
    cudaGetSymbolAddress((void**)&Qc,   g_Qc);
    cudaGetSymbolAddress((void**)&o32a, g_o32a);
    cudaGetSymbolAddress((void**)&o32c, g_o32c);
    cudaGetSymbolAddress((void**)&X2,   g_X2);
    cudaGetSymbolAddress((void**)&AO,   g_AO);
    cudaGetSymbolAddress((void**)&F,    g_F);
    cudaGetSymbolAddress((void**)&hout, g_hout);
    float* Xm; cudaGetSymbolAddress((void**)&Xm, g_X);

    // 1. time embeddings
    emb_kernel<<<NB*NL + 128, 128>>>(ts, w_per, b_per, w_lin, b_lin);

    // 2. K/Q projections (3 GEMMs in one launch)
    kq_gemm_kernel<<<dim3(64, 2, 3), 256>>>(Wq_t, bq_t, Wk_t, bk_t);

    // 3. masked channel attention (main + cls in one launch)
    mta_kernel<<<dim3(10, NB*2), 256>>>(Qb, Qc, Kb, x, o32a, o32c);

    // 4. build merged tblock input (includes cls-row fill)
    proj32_kernel<<<161, 256>>>(o32a, o32c, Wo_t, bo_t, pos_emb, cls_emb);

    // 5. merged tblock (both T=129 and T=513 at once, same weights)
    qkv_gemm_kernel<<<dim3((MTR+63)/64, 2, 3), 256>>>(tWq, tbq, tWk, tbk, tWv, tbv);
    tattn_kernel<<<dim3((NT2+63)/64, 32), 256>>>();
    gemm_ln_kernel<<<(MTR+31)/32, 256>>>(AO, tWo, tbo, Xm, ln1_g, ln1_b, X2, nullptr, nullptr, 0);
    gemm_kernel<<<dim3((MTR+63)/64, 2), 256>>>(X2, fW1, fb1, F, MTR, 1);
    gemm_ln_kernel<<<(MTR+31)/32, 256>>>(F, fW2, fb2, X2, ln2_g, ln2_b, nullptr, dout + 1024, hout, 1);

    // 6. cls pooling -> dout[0:1024]
    pool_kernel<<<NB, 128>>>(pW, pb, dout);
}

// round 5
// speedup vs baseline: 1.1130x; 1.1130x over previous
#include <cuda_runtime.h>
#include <math.h>

#define NB 8
#define NL 512
#define NE 128
#define NT1 129
#define NT2 513
#define M1R (NB*NT1)        // 1032
#define M2R (NB*NT2)        // 4104
#define MTR (M1R+M2R)       // 5136

// ---------------- device scratch ----------------
__device__ float g_key_e[NB*NL*NE];
__device__ float g_clsq [128*NE];
__device__ float g_Qb   [NB*NL*NE];
__device__ float g_Kb   [NB*NL*NE];
__device__ float g_Qc   [128*NE];
__device__ float g_o32a [NB*NL*32];
__device__ float g_o32c [NB*128*32];
__device__ float g_X    [MTR*128];
__device__ float g_Q    [MTR*128];
__device__ float g_K    [MTR*128];
__device__ float g_V    [MTR*128];
__device__ float g_AO   [MTR*128];
__device__ float g_X2   [MTR*128];
__device__ float g_F    [MTR*128];
__device__ float g_hout [M1R*128];

// ---------------- time embedding ----------------
__global__ void emb_kernel(const float* __restrict__ ts,
                           const float* __restrict__ w_per, const float* __restrict__ b_per,
                           const float* __restrict__ w_lin, const float* __restrict__ b_lin)
{
    int row = blockIdx.x, j = threadIdx.x;
    float t; float* dst;
    if (row < NB*NL) { t = ts[row]; dst = g_key_e + (size_t)row*NE; }
    else             { int i = row - NB*NL; t = (float)i * (1.0f/127.0f); dst = g_clsq + (size_t)i*NE; }
    float v;
    if (j == 0) v = t*w_lin[0] + b_lin[0];
    else        v = sinf(t*w_per[j-1] + b_per[j-1]);
    dst[j] = v;
}

// ---------------- 64x64-tile SGEMM body (K=N=128) ----------------
__device__ __forceinline__ void gemm64x64(const float* __restrict__ A, const float* __restrict__ W,
                                          const float* __restrict__ bias, float* __restrict__ C,
                                          int M, int relu)
{
    __shared__ float As[16][64];
    __shared__ float Ws[16][64];
    const int tid = threadIdx.x;            // 256 threads
    const int tn = tid & 15, tm = tid >> 4;
    const int m0 = blockIdx.x * 64, n0 = blockIdx.y * 64;
    float acc[4][4];
    #pragma unroll
    for (int i=0;i<4;i++)
        #pragma unroll
        for (int j=0;j<4;j++) acc[i][j] = 0.f;

    const int la  = tid * 4;
    const int lar = la >> 4, lac = la & 15;
    const int lwr = la >> 6, lwc = la & 63;

    for (int kk = 0; kk < 128; kk += 16) {
        float4 av = make_float4(0.f,0.f,0.f,0.f);
        int gm = m0 + lar;
        if (gm < M) av = *(const float4*)(A + (size_t)gm*128 + kk + lac);
        float4 wv = *(const float4*)(W + (size_t)(kk+lwr)*128 + n0 + lwc);
        __syncthreads();
        As[lac+0][lar]=av.x; As[lac+1][lar]=av.y; As[lac+2][lar]=av.z; As[lac+3][lar]=av.w;
        *(float4*)&Ws[lwr][lwc] = wv;
        __syncthreads();
        #pragma unroll
        for (int k=0;k<16;k++) {
            float a[4], b[4];
            *(float4*)a = *(const float4*)&As[k][tm*4];
            *(float4*)b = *(const float4*)&Ws[k][tn*4];
            #pragma unroll
            for (int i=0;i<4;i++)
                #pragma unroll
                for (int j=0;j<4;j++) acc[i][j] = fmaf(a[i], b[j], acc[i][j]);
        }
    }
    float4 bv4 = *(const float4*)(bias + n0 + tn*4);
    float bb[4] = {bv4.x, bv4.y, bv4.z, bv4.w};
    #pragma unroll
    for (int i=0;i<4;i++) {
        int gm = m0 + tm*4 + i;
        if (gm < M) {
            float4 o;
            o.x = acc[i][0]+bb[0]; o.y = acc[i][1]+bb[1];
            o.z = acc[i][2]+bb[2]; o.w = acc[i][3]+bb[3];
            if (relu) { o.x=fmaxf(o.x,0.f); o.y=fmaxf(o.y,0.f); o.z=fmaxf(o.z,0.f); o.w=fmaxf(o.w,0.f); }
            *(float4*)(C + (size_t)gm*128 + n0 + tn*4) = o;
        }
    }
}

// K/Q projections of embeddings (z=0: Kb, z=1: Qb, z=2: Qc)
__global__ void kq_gemm_kernel(const float* __restrict__ Wq, const float* __restrict__ bq,
                               const float* __restrict__ Wk, const float* __restrict__ bk)
{
    const float *A, *W, *bias; float* C; int M;
    if (blockIdx.z == 0)      { A=g_key_e; W=Wk; bias=bk; C=g_Kb; M=NB*NL; }
    else if (blockIdx.z == 1) { A=g_key_e; W=Wq; bias=bq; C=g_Qb; M=NB*NL; }
    else                      { A=g_clsq;  W=Wq; bias=bq; C=g_Qc; M=128;  }
    if (blockIdx.x*64 >= M) return;
    gemm64x64(A, W, bias, C, M, 0);
}

// QKV for merged tblock rows (z selects q/k/v)
__global__ void qkv_gemm_kernel(const float* __restrict__ Wq, const float* __restrict__ bq,
                                const float* __restrict__ Wk, const float* __restrict__ bk,
                                const float* __restrict__ Wv, const float* __restrict__ bv)
{
    const float *W, *bias; float* C;
    if (blockIdx.z == 0)      { W=Wq; bias=bq; C=g_Q; }
    else if (blockIdx.z == 1) { W=Wk; bias=bk; C=g_K; }
    else                      { W=Wv; bias=bv; C=g_V; }
    gemm64x64(g_X, W, bias, C, MTR, 0);
}

__global__ void gemm_kernel(const float* __restrict__ A, const float* __restrict__ W,
                            const float* __restrict__ bias, float* __restrict__ C,
                            int M, int relu)
{
    gemm64x64(A, W, bias, C, M, relu);
}

// ---------------- GEMM (32x128 tile) + bias + residual + LayerNorm ----------------
__global__ void gemm_ln_kernel(const float* __restrict__ A, const float* __restrict__ W,
                               const float* __restrict__ bias, const float* __restrict__ Res,
                               const float* __restrict__ lng, const float* __restrict__ lnb,
                               float* __restrict__ out, float* __restrict__ dlast,
                               float* __restrict__ hout, int mode)
{
    __shared__ float As[16][32];
    __shared__ float Ws[16][128];
    const int tid = threadIdx.x;          // 256 threads
    const int tn = tid & 31, tm = tid >> 5;
    const int m0 = blockIdx.x * 32;
    float acc[4][4];
    #pragma unroll
    for (int i=0;i<4;i++)
        #pragma unroll
        for (int j=0;j<4;j++) acc[i][j] = 0.f;

    const int lam = tid & 31, lak = (tid >> 5) * 2;

    for (int kk = 0; kk < 128; kk += 16) {
        float2 av = make_float2(0.f,0.f);
        int gm = m0 + lam;
        if (gm < MTR) av = *(const float2*)(A + (size_t)gm*128 + kk + lak);
        float4 wv0, wv1;
        {
            int i0 = tid*4;
            wv0 = *(const float4*)(W + (size_t)(kk + (i0>>7))*128 + (i0&127));
            int i1 = tid*4 + 1024;
            wv1 = *(const float4*)(W + (size_t)(kk + (i1>>7))*128 + (i1&127));
        }
        __syncthreads();
        As[lak][lam] = av.x; As[lak+1][lam] = av.y;
        { int i0 = tid*4;        *(float4*)&Ws[i0>>7][i0&127] = wv0; }
        { int i1 = tid*4 + 1024; *(float4*)&Ws[i1>>7][i1&127] = wv1; }
        __syncthreads();
        #pragma unroll
        for (int k=0;k<16;k++) {
            float a[4], b[4];
            *(float4*)a = *(const float4*)&As[k][tm*4];
            *(float4*)b = *(const float4*)&Ws[k][tn*4];
            #pragma unroll
            for (int i=0;i<4;i++)
                #pragma unroll
                for (int j=0;j<4;j++) acc[i][j] = fmaf(a[i], b[j], acc[i][j]);
        }
    }

    float4 bb4 = *(const float4*)(bias + tn*4);
    float bb[4] = {bb4.x, bb4.y, bb4.z, bb4.w};
    float4 g4 = *(const float4*)(lng + tn*4);
    float4 be4 = *(const float4*)(lnb + tn*4);
    float gg[4] = {g4.x, g4.y, g4.z, g4.w};
    float lb[4] = {be4.x, be4.y, be4.z, be4.w};

    #pragma unroll
    for (int i=0;i<4;i++) {
        int r = m0 + tm*4 + i;
        if (r >= MTR) continue;
        float4 rv = *(const float4*)(Res + (size_t)r*128 + tn*4);
        float v[4];
        v[0] = acc[i][0] + bb[0] + rv.x;
        v[1] = acc[i][1] + bb[1] + rv.y;
        v[2] = acc[i][2] + bb[2] + rv.z;
        v[3] = acc[i][3] + bb[3] + rv.w;
        float s = v[0]+v[1]+v[2]+v[3];
        float s2 = v[0]*v[0]+v[1]*v[1]+v[2]*v[2]+v[3]*v[3];
        #pragma unroll
        for (int off=16; off>0; off>>=1) {
            s  += __shfl_xor_sync(0xffffffffu, s,  off);
            s2 += __shfl_xor_sync(0xffffffffu, s2, off);
        }
        float mean = s * (1.f/128.f);
        float var  = s2 * (1.f/128.f) - mean*mean;
        float rs   = rsqrtf(var + 1e-5f);
        float4 o;
        o.x = (v[0]-mean)*rs*gg[0] + lb[0];
        o.y = (v[1]-mean)*rs*gg[1] + lb[1];
        o.z = (v[2]-mean)*rs*gg[2] + lb[2];
        o.w = (v[3]-mean)*rs*gg[3] + lb[3];
        if (mode == 0) {
            *(float4*)(out + (size_t)r*128 + tn*4) = o;
        } else {
            if (r < M1R) {
                *(float4*)(hout + (size_t)r*128 + tn*4) = o;
            } else {
                int rr = r - M1R;
                int t  = rr % NT2;
                if (t == 0) continue;
                int b  = rr / NT2;
                *(float4*)(dlast + ((size_t)b*NL + t - 1)*128 + tn*4) = o;
            }
        }
    }
}

// ---------------- masked per-channel attention (mTA), 4-way KEY split ----------------
// 256 threads: 64 queries x 4 key-quarters; full 64-dim dot per thread (shfl-free inner loop)
__global__ void __launch_bounds__(256, 1)
mta_kernel(const float* __restrict__ Qmain, const float* __restrict__ Qcls,
           const float* __restrict__ K, const float* __restrict__ X,
           float* __restrict__ o32main, float* __restrict__ o32cls)
{
    const int bh = blockIdx.y, b = bh >> 1, h = bh & 1;
    const bool cls = blockIdx.x >= 8;
    const int tile = cls ? (blockIdx.x - 8) : blockIdx.x;
    const float* Q = cls ? Qcls : Qmain;
    const int qStride = cls ? 0 : NL*128;
    const int Lq = cls ? 128 : NL;
    float* o32 = cls ? o32cls : o32main;

    const int tid = threadIdx.x, lane = tid & 31, warp = tid >> 5;
    const int qsub = lane & 7;
    const int quar = lane >> 3;               // 0..3 key quarter (128 keys each)
    const int qi = tile*64 + warp*8 + qsub;

    __shared__ float sK[4][16][64];
    __shared__ float sX[4][16][16];

    float4 qreg[16];
    const float* qp = Q + (size_t)b*qStride + (size_t)qi*128 + h*64;
    #pragma unroll
    for (int i=0;i<16;i++) qreg[i] = *(const float4*)(qp + i*4);

    float m = -1e30f;
    float den[8], num[8];
    #pragma unroll
    for (int c=0;c<8;c++){ den[c]=0.f; num[c]=0.f; }

    for (int c=0;c<8;c++) {            // 16 keys per quarter per chunk
        __syncthreads();
        #pragma unroll
        for (int u=0;u<4;u++) {
            int e = (tid*4+u)*4;                 // 0..4092 floats (4096 total)
            int hh = e>>10, kk = (e>>6)&15, d = e&63;
            int kglob = hh*128 + c*16 + kk;
            *(float4*)&sK[hh][kk][d] =
                *(const float4*)(K + ((size_t)b*NL + kglob)*128 + h*64 + d);
        }
        {
            int e = tid*4;                       // 0..1020 floats (1024 total)
            int hh = e>>8, kk = (e>>4)&15, d = e&15;
            int kglob = hh*128 + c*16 + kk;
            *(float4*)&sX[hh][kk][d] =
                *(const float4*)(X + ((size_t)b*NL + kglob)*16 + d);
        }
        __syncthreads();
        #pragma unroll 2
        for (int kk=0;kk<16;kk++) {
            const float4* kr = (const float4*)sK[quar][kk];
            float4 a4 = make_float4(0.f,0.f,0.f,0.f);
            #pragma unroll
            for (int i=0;i<16;i++) {
                float4 kv = kr[i];
                a4.x = fmaf(kv.x, qreg[i].x, a4.x);
                a4.y = fmaf(kv.y, qreg[i].y, a4.y);
                a4.z = fmaf(kv.z, qreg[i].z, a4.z);
                a4.w = fmaf(kv.w, qreg[i].w, a4.w);
            }
            float s = ((a4.x+a4.y)+(a4.z+a4.w))*0.125f;
            if (s > m) {
                float f = __expf(m - s);
                #pragma unroll
                for (int cc=0;cc<8;cc++){ den[cc]*=f; num[cc]*=f; }
                m = s;
            }
            float e = __expf(s - m);
            const float* xr = sX[quar][kk];
            #pragma unroll
            for (int cc=0;cc<8;cc++) {
                float t = e * xr[8+cc];
                den[cc] += t;
                num[cc] = fmaf(t, xr[cc], num[cc]);
            }
        }
    }
    // merge 4 key-quarters: stages xor 8 then xor 16
    #pragma unroll
    for (int off=8; off<=16; off<<=1) {
        float m2 = __shfl_xor_sync(0xffffffffu, m, off);
        float Mx = fmaxf(m, m2);
        float f1 = __expf(m - Mx), f2 = __expf(m2 - Mx);
        #pragma unroll
        for (int cc=0;cc<8;cc++) {
            float d2 = __shfl_xor_sync(0xffffffffu, den[cc], off);
            float n2 = __shfl_xor_sync(0xffffffffu, num[cc], off);
            den[cc] = den[cc]*f1 + d2*f2;
            num[cc] = num[cc]*f1 + n2*f2;
        }
        m = Mx;
    }
    if (quar == 0) {
        float res[16];
        #pragma unroll
        for (int cc=0;cc<8;cc++) {
            bool ok = den[cc] > 0.f;
            res[cc]   = ok ? num[cc]/den[cc] : 0.f;
            res[8+cc] = ok ? 1.f : 0.f;
        }
        float* dst = o32 + ((size_t)b*Lq + qi)*32 + h*16;
        #pragma unroll
        for (int i=0;i<4;i++)
            *(float4*)(dst + i*4) = make_float4(res[i*4],res[i*4+1],res[i*4+2],res[i*4+3]);
    }
}

// ---------------- 32->128 projection into merged X + cls-row fill (16 rows/block) ----
__global__ void proj32_kernel(const float* __restrict__ Am, const float* __restrict__ Ac,
                              const float* __restrict__ W, const float* __restrict__ bias,
                              const float* __restrict__ pos, const float* __restrict__ cls_emb)
{
    if (blockIdx.x == 320) {     // cls token rows for both parts
        for (int i = threadIdx.x; i < 1024; i += 256) {
            int b = i >> 7, j = i & 127;
            float cv = cls_emb[j];
            g_X[((size_t)b*NT1)*128 + j] = cv;
            g_X[((size_t)M1R + (size_t)b*NT2)*128 + j] = cv + pos[j];
        }
        return;
    }
    __shared__ float sW[32*128];
    __shared__ float sA[16*32];
    const bool cls = blockIdx.x >= 256;
    const float* A = cls ? Ac : Am;
    const int Lq = cls ? 128 : NL;
    const int r0 = (cls ? (blockIdx.x - 256) : blockIdx.x) * 16;
    for (int i = threadIdx.x; i < 4096; i += 256) sW[i] = W[i];
    for (int i = threadIdx.x; i < 512; i += 256)
        sA[i] = A[(size_t)(r0 + (i >> 5))*32 + (i & 31)];
    __syncthreads();
    #pragma unroll
    for (int u=0;u<8;u++) {
        int oi = threadIdx.x + u*256;
        int lr = oi >> 7, col = oi & 127;
        int r = r0 + lr;
        float acc = bias[col];
        #pragma unroll
        for (int k=0;k<32;k++) acc = fmaf(sA[lr*32+k], sW[k*128+col], acc);
        int bb = r / Lq, q = r % Lq;
        size_t row;
        if (cls) row = (size_t)bb*NT1 + 1 + q;
        else   { row = (size_t)M1R + (size_t)bb*NT2 + 1 + q; acc += pos[(size_t)(1+q)*128 + col]; }
        g_X[row*128 + col] = acc;
    }
}

// ---------------- transformer-block attention, 4-way KEY split ----------------
// 256 threads: 64 queries x 4 key-quarters; full 64-dim dot + o[64] per thread
__global__ void __launch_bounds__(256, 1) tattn_kernel()
{
    const int y = blockIdx.y;
    const int part = y >> 4;              // 0: T1 block, 1: T2 block
    const int bh = y & 15, b = bh >> 1, h = bh & 1;
    const int T = part ? NT2 : NT1;
    const int base = part ? (M1R + b*NT2) : (b*NT1);
    if (blockIdx.x * 64 >= T) return;

    const int tid = threadIdx.x, lane = tid & 31, warp = tid >> 5;
    const int qsub = lane & 7;
    const int quar = lane >> 3;           // 0..3 key quarter
    const int qi = blockIdx.x*64 + warp*8 + qsub;

    __shared__ float sK[4][16][64];
    __shared__ float sV[4][16][64];

    float4 qreg[16];
    if (qi < T) {
        const float* qp = g_Q + ((size_t)base + qi)*128 + h*64;
        #pragma unroll
        for (int i=0;i<16;i++) qreg[i] = *(const float4*)(qp + i*4);
    } else {
        #pragma unroll
        for (int i=0;i<16;i++) qreg[i] = make_float4(0.f,0.f,0.f,0.f);
    }
    float m = -1e30f, l = 0.f;
    float o[64];
    #pragma unroll
    for (int d=0;d<64;d++) o[d]=0.f;

    const int qlen = (T + 3) >> 2;
    const int kend  = min((quar+1)*qlen, T);
    const int nch = (qlen + 15) >> 4;

    for (int c=0;c<nch;c++) {
        __syncthreads();
        #pragma unroll
        for (int u=0;u<8;u++) {
            int e = (tid*8 + u)*4;            // 0..8188 (8192 floats K+V)
            int isV = e >> 12;
            int e2 = e & 4095;
            int hh = e2 >> 10, kk = (e2 >> 6) & 15, d = e2 & 63;
            int kglob = hh*qlen + c*16 + kk;
            int lim = min((hh+1)*qlen, T);
            float4 v = make_float4(0.f,0.f,0.f,0.f);
            if (kglob < lim) {
                const float* src = (isV ? g_V : g_K) + ((size_t)base + kglob)*128 + h*64 + d;
                v = *(const float4*)src;
            }
            float* dst = isV ? &sV[hh][kk][d] : &sK[hh][kk][d];
            *(float4*)dst = v;
        }
        __syncthreads();
        const int k0 = quar*qlen + c*16;
        #pragma unroll 2
        for (int kk=0;kk<16;kk++) {
            const float4* kr = (const float4*)sK[quar][kk];
            float4 a4 = make_float4(0.f,0.f,0.f,0.f);
            #pragma unroll
            for (int i=0;i<16;i++) {
                float4 kv = kr[i];
                a4.x = fmaf(kv.x, qreg[i].x, a4.x);
                a4.y = fmaf(kv.y, qreg[i].y, a4.y);
                a4.z = fmaf(kv.z, qreg[i].z, a4.z);
                a4.w = fmaf(kv.w, qreg[i].w, a4.w);
            }
            float s = ((a4.x+a4.y)+(a4.z+a4.w))*0.125f;
            if (k0 + kk < kend) {
                if (s > m) {
                    float f = __expf(m - s);
                    l *= f;
                    #pragma unroll
                    for (int d=0;d<64;d++) o[d]*=f;
                    m = s;
                }
                float e = __expf(s - m);
                l += e;
                const float4* vr = (const float4*)sV[quar][kk];
                #pragma unroll
                for (int i=0;i<16;i++) {
                    float4 vv = vr[i];
                    o[i*4+0] = fmaf(e, vv.x, o[i*4+0]);
                    o[i*4+1] = fmaf(e, vv.y, o[i*4+1]);
                    o[i*4+2] = fmaf(e, vv.z, o[i*4+2]);
                    o[i*4+3] = fmaf(e, vv.w, o[i*4+3]);
                }
            }
        }
    }
    // merge 4 key-quarters: stages xor 8 then xor 16
    #pragma unroll
    for (int off=8; off<=16; off<<=1) {
        float m2 = __shfl_xor_sync(0xffffffffu, m, off);
        float Mx = fmaxf(m, m2);
        float f1 = __expf(m - Mx), f2 = __expf(m2 - Mx);
        float l2 = __shfl_xor_sync(0xffffffffu, l, off);
        l = l*f1 + l2*f2;
        #pragma unroll
        for (int d=0;d<64;d++) {
            float o2 = __shfl_xor_sync(0xffffffffu, o[d], off);
            o[d] = o[d]*f1 + o2*f2;
        }
        m = Mx;
    }
    if (quar == 0 && qi < T) {
        float inv = 1.0f / l;
        float* dst = g_AO + ((size_t)base + qi)*128 + h*64;
        #pragma unroll
        for (int i=0;i<16;i++)
            *(float4*)(dst + i*4) = make_float4(o[i*4]*inv, o[i*4+1]*inv, o[i*4+2]*inv, o[i*4+3]*inv);
    }
}

// ---------------- cls pooling ----------------
__global__ void pool_kernel(const float* __restrict__ pW,
                            const float* __restrict__ pb, float* __restrict__ dout)
{
    int b = blockIdx.x, j = threadIdx.x;
    __shared__ float s[128];
    s[j] = g_hout[((size_t)b*NT1)*128 + j];
    __syncthreads();
    float acc = pb[j];
    #pragma unroll
    for (int k=0;k<128;k++) acc = fmaf(s[k], pW[k*128 + j], acc);
    dout[b*128 + j] = tanhf(acc);
}

// ---------------- launch ----------------
extern "C" void kernel_launch(void* const* d_in, const int* in_sizes, int n_in,
                              void* d_out, int out_size)
{
    (void)in_sizes; (void)n_in; (void)out_size;
    const float* x       = (const float*)d_in[0];
    const float* ts      = (const float*)d_in[1];
    const float* w_per   = (const float*)d_in[2];
    const float* b_per   = (const float*)d_in[3];
    const float* w_lin   = (const float*)d_in[4];
    const float* b_lin   = (const float*)d_in[5];
    const float* Wq_t    = (const float*)d_in[6];
    const float* bq_t    = (const float*)d_in[7];
    const float* Wk_t    = (const float*)d_in[8];
    const float* bk_t    = (const float*)d_in[9];
    const float* Wo_t    = (const float*)d_in[10];
    const float* bo_t    = (const float*)d_in[11];
    const float* pos_emb = (const float*)d_in[12];
    const float* cls_emb = (const float*)d_in[13];
    const float* tWq = (const float*)d_in[14];
    const float* tbq = (const float*)d_in[15];
    const float* tWk = (const float*)d_in[16];
    const float* tbk = (const float*)d_in[17];
    const float* tWv = (const float*)d_in[18];
    const float* tbv = (const float*)d_in[19];
    const float* tWo = (const float*)d_in[20];
    const float* tbo = (const float*)d_in[21];
    const float* ln1_g = (const float*)d_in[22];
    const float* ln1_b = (const float*)d_in[23];
    const float* fW1 = (const float*)d_in[24];
    const float* fb1 = (const float*)d_in[25];
    const float* fW2 = (const float*)d_in[26];
    const float* fb2 = (const float*)d_in[27];
    const float* ln2_g = (const float*)d_in[28];
    const float* ln2_b = (const float*)d_in[29];
    const float* pW  = (const float*)d_in[30];
    const float* pb  = (const float*)d_in[31];
    float* dout = (float*)d_out;

    float *Qb, *Kb, *Qc, *o32a, *o32c, *X2, *AO, *F, *hout;
    cudaGetSymbolAddress((void**)&Qb,   g_Qb);
    cudaGetSymbolAddress((void**)&Kb,   g_Kb);
    cudaGetSymbolAddress((void**)&Qc,   g_Qc);
    cudaGetSymbolAddress((void**)&o32a, g_o32a);
    cudaGetSymbolAddress((void**)&o32c, g_o32c);
    cudaGetSymbolAddress((void**)&X2,   g_X2);
    cudaGetSymbolAddress((void**)&AO,   g_AO);
    cudaGetSymbolAddress((void**)&F,    g_F);
    cudaGetSymbolAddress((void**)&hout, g_hout);
    float* Xm; cudaGetSymbolAddress((void**)&Xm, g_X);

    // 1. time embeddings
    emb_kernel<<<NB*NL + 128, 128>>>(ts, w_per, b_per, w_lin, b_lin);

    // 2. K/Q projections (3 GEMMs in one launch)
    kq_gemm_kernel<<<dim3(64, 2, 3), 256>>>(Wq_t, bq_t, Wk_t, bk_t);

    // 3. masked channel attention (main + cls in one launch)
    mta_kernel<<<dim3(10, NB*2), 256>>>(Qb, Qc, Kb, x, o32a, o32c);

    // 4. build merged tblock input (includes cls-row fill)
    proj32_kernel<<<321, 256>>>(o32a, o32c, Wo_t, bo_t, pos_emb, cls_emb);

    // 5. merged tblock (both T=129 and T=513 at once, same weights)
    qkv_gemm_kernel<<<dim3((MTR+63)/64, 2, 3), 256>>>(tWq, tbq, tWk, tbk, tWv, tbv);
    tattn_kernel<<<dim3((NT2+63)/64, 32), 256>>>();
    gemm_ln_kernel<<<(MTR+31)/32, 256>>>(AO, tWo, tbo, Xm, ln1_g, ln1_b, X2, nullptr, nullptr, 0);
    gemm_kernel<<<dim3((MTR+63)/64, 2), 256>>>(X2, fW1, fb1, F, MTR, 1);
    gemm_ln_kernel<<<(MTR+31)/32, 256>>>(F, fW2, fb2, X2, ln2_g, ln2_b, nullptr, dout + 1024, hout, 1);

    // 6. cls pooling -> dout[0:1024]
    pool_kernel<<<NB, 128>>>(pW, pb, dout);
}

// round 6
// speedup vs baseline: 1.2472x; 1.1205x over previous
#include <cuda_runtime.h>
#include <math.h>

#define NB 8
#define NL 512
#define NE 128
#define NT1 129
#define NT2 513
#define M1R (NB*NT1)        // 1032
#define M2R (NB*NT2)        // 4104
#define MTR (M1R+M2R)       // 5136

// ---------------- device scratch ----------------
__device__ float g_key_e[NB*NL*NE];
__device__ float g_clsq [128*NE];
__device__ float g_Qb   [NB*NL*NE];
__device__ float g_Kb   [NB*NL*NE];
__device__ float g_Qc   [128*NE];
__device__ float g_o32a [NB*NL*32];
__device__ float g_o32c [NB*128*32];
__device__ float g_X    [MTR*128];
__device__ float g_Q    [MTR*128];
__device__ float g_K    [MTR*128];
__device__ float g_V    [MTR*128];
__device__ float g_AO   [MTR*128];
__device__ float g_X2   [MTR*128];
__device__ float g_F    [MTR*128];
__device__ float g_hout [M1R*128];

// ---------------- fast exp on FMA/ALU pipes (args <= 0) ----------------
// exp(x) = 2^(x*log2e); round via magic constant, degree-5 poly for 2^f, |f|<=0.5
__device__ __forceinline__ float fexp(float x)
{
    x = fmaxf(x, -80.0f);
    float t  = x * 1.4426950408889634f;
    float kf = t + 12582912.0f;                       // 2^23+2^22 magic (RN)
    int   k  = __float_as_int(kf) - 0x4B400000;
    float f  = t - (kf - 12582912.0f);                // f in [-0.5, 0.5]
    float p  = 1.3333558e-3f;
    p = fmaf(p, f, 9.6181291e-3f);
    p = fmaf(p, f, 5.5504109e-2f);
    p = fmaf(p, f, 2.4022651e-1f);
    p = fmaf(p, f, 6.9314718e-1f);
    p = fmaf(p, f, 1.0f);
    return __int_as_float(__float_as_int(p) + (k << 23));
}

// ---------------- time embedding ----------------
__global__ void emb_kernel(const float* __restrict__ ts,
                           const float* __restrict__ w_per, const float* __restrict__ b_per,
                           const float* __restrict__ w_lin, const float* __restrict__ b_lin)
{
    int row = blockIdx.x, j = threadIdx.x;
    float t; float* dst;
    if (row < NB*NL) { t = ts[row]; dst = g_key_e + (size_t)row*NE; }
    else             { int i = row - NB*NL; t = (float)i * (1.0f/127.0f); dst = g_clsq + (size_t)i*NE; }
    float v;
    if (j == 0) v = t*w_lin[0] + b_lin[0];
    else        v = sinf(t*w_per[j-1] + b_per[j-1]);
    dst[j] = v;
}

// ---------------- 64x64-tile SGEMM body (K=N=128) ----------------
__device__ __forceinline__ void gemm64x64(const float* __restrict__ A, const float* __restrict__ W,
                                          const float* __restrict__ bias, float* __restrict__ C,
                                          int M, int relu)
{
    __shared__ float As[16][64];
    __shared__ float Ws[16][64];
    const int tid = threadIdx.x;            // 256 threads
    const int tn = tid & 15, tm = tid >> 4;
    const int m0 = blockIdx.x * 64, n0 = blockIdx.y * 64;
    float acc[4][4];
    #pragma unroll
    for (int i=0;i<4;i++)
        #pragma unroll
        for (int j=0;j<4;j++) acc[i][j] = 0.f;

    const int la  = tid * 4;
    const int lar = la >> 4, lac = la & 15;
    const int lwr = la >> 6, lwc = la & 63;

    for (int kk = 0; kk < 128; kk += 16) {
        float4 av = make_float4(0.f,0.f,0.f,0.f);
        int gm = m0 + lar;
        if (gm < M) av = *(const float4*)(A + (size_t)gm*128 + kk + lac);
        float4 wv = *(const float4*)(W + (size_t)(kk+lwr)*128 + n0 + lwc);
        __syncthreads();
        As[lac+0][lar]=av.x; As[lac+1][lar]=av.y; As[lac+2][lar]=av.z; As[lac+3][lar]=av.w;
        *(float4*)&Ws[lwr][lwc] = wv;
        __syncthreads();
        #pragma unroll
        for (int k=0;k<16;k++) {
            float a[4], b[4];
            *(float4*)a = *(const float4*)&As[k][tm*4];
            *(float4*)b = *(const float4*)&Ws[k][tn*4];
            #pragma unroll
            for (int i=0;i<4;i++)
                #pragma unroll
                for (int j=0;j<4;j++) acc[i][j] = fmaf(a[i], b[j], acc[i][j]);
        }
    }
    float4 bv4 = *(const float4*)(bias + n0 + tn*4);
    float bb[4] = {bv4.x, bv4.y, bv4.z, bv4.w};
    #pragma unroll
    for (int i=0;i<4;i++) {
        int gm = m0 + tm*4 + i;
        if (gm < M) {
            float4 o;
            o.x = acc[i][0]+bb[0]; o.y = acc[i][1]+bb[1];
            o.z = acc[i][2]+bb[2]; o.w = acc[i][3]+bb[3];
            if (relu) { o.x=fmaxf(o.x,0.f); o.y=fmaxf(o.y,0.f); o.z=fmaxf(o.z,0.f); o.w=fmaxf(o.w,0.f); }
            *(float4*)(C + (size_t)gm*128 + n0 + tn*4) = o;
        }
    }
}

// K/Q projections of embeddings (z=0: Kb, z=1: Qb, z=2: Qc)
__global__ void kq_gemm_kernel(const float* __restrict__ Wq, const float* __restrict__ bq,
                               const float* __restrict__ Wk, const float* __restrict__ bk)
{
    const float *A, *W, *bias; float* C; int M;
    if (blockIdx.z == 0)      { A=g_key_e; W=Wk; bias=bk; C=g_Kb; M=NB*NL; }
    else if (blockIdx.z == 1) { A=g_key_e; W=Wq; bias=bq; C=g_Qb; M=NB*NL; }
    else                      { A=g_clsq;  W=Wq; bias=bq; C=g_Qc; M=128;  }
    if (blockIdx.x*64 >= M) return;
    gemm64x64(A, W, bias, C, M, 0);
}

// QKV for merged tblock rows (z selects q/k/v)
__global__ void qkv_gemm_kernel(const float* __restrict__ Wq, const float* __restrict__ bq,
                                const float* __restrict__ Wk, const float* __restrict__ bk,
                                const float* __restrict__ Wv, const float* __restrict__ bv)
{
    const float *W, *bias; float* C;
    if (blockIdx.z == 0)      { W=Wq; bias=bq; C=g_Q; }
    else if (blockIdx.z == 1) { W=Wk; bias=bk; C=g_K; }
    else                      { W=Wv; bias=bv; C=g_V; }
    gemm64x64(g_X, W, bias, C, MTR, 0);
}

__global__ void gemm_kernel(const float* __restrict__ A, const float* __restrict__ W,
                            const float* __restrict__ bias, float* __restrict__ C,
                            int M, int relu)
{
    gemm64x64(A, W, bias, C, M, relu);
}

// ---------------- GEMM (32x128 tile) + bias + residual + LayerNorm ----------------
__global__ void gemm_ln_kernel(const float* __restrict__ A, const float* __restrict__ W,
                               const float* __restrict__ bias, const float* __restrict__ Res,
                               const float* __restrict__ lng, const float* __restrict__ lnb,
                               float* __restrict__ out, float* __restrict__ dlast,
                               float* __restrict__ hout, int mode)
{
    __shared__ float As[16][32];
    __shared__ float Ws[16][128];
    const int tid = threadIdx.x;          // 256 threads
    const int tn = tid & 31, tm = tid >> 5;
    const int m0 = blockIdx.x * 32;
    float acc[4][4];
    #pragma unroll
    for (int i=0;i<4;i++)
        #pragma unroll
        for (int j=0;j<4;j++) acc[i][j] = 0.f;

    const int lam = tid & 31, lak = (tid >> 5) * 2;

    for (int kk = 0; kk < 128; kk += 16) {
        float2 av = make_float2(0.f,0.f);
        int gm = m0 + lam;
        if (gm < MTR) av = *(const float2*)(A + (size_t)gm*128 + kk + lak);
        float4 wv0, wv1;
        {
            int i0 = tid*4;
            wv0 = *(const float4*)(W + (size_t)(kk + (i0>>7))*128 + (i0&127));
            int i1 = tid*4 + 1024;
            wv1 = *(const float4*)(W + (size_t)(kk + (i1>>7))*128 + (i1&127));
        }
        __syncthreads();
        As[lak][lam] = av.x; As[lak+1][lam] = av.y;
        { int i0 = tid*4;        *(float4*)&Ws[i0>>7][i0&127] = wv0; }
        { int i1 = tid*4 + 1024; *(float4*)&Ws[i1>>7][i1&127] = wv1; }
        __syncthreads();
        #pragma unroll
        for (int k=0;k<16;k++) {
            float a[4], b[4];
            *(float4*)a = *(const float4*)&As[k][tm*4];
            *(float4*)b = *(const float4*)&Ws[k][tn*4];
            #pragma unroll
            for (int i=0;i<4;i++)
                #pragma unroll
                for (int j=0;j<4;j++) acc[i][j] = fmaf(a[i], b[j], acc[i][j]);
        }
    }

    float4 bb4 = *(const float4*)(bias + tn*4);
    float bb[4] = {bb4.x, bb4.y, bb4.z, bb4.w};
    float4 g4 = *(const float4*)(lng + tn*4);
    float4 be4 = *(const float4*)(lnb + tn*4);
    float gg[4] = {g4.x, g4.y, g4.z, g4.w};
    float lb[4] = {be4.x, be4.y, be4.z, be4.w};

    #pragma unroll
    for (int i=0;i<4;i++) {
        int r = m0 + tm*4 + i;
        if (r >= MTR) continue;
        float4 rv = *(const float4*)(Res + (size_t)r*128 + tn*4);
        float v[4];
        v[0] = acc[i][0] + bb[0] + rv.x;
        v[1] = acc[i][1] + bb[1] + rv.y;
        v[2] = acc[i][2] + bb[2] + rv.z;
        v[3] = acc[i][3] + bb[3] + rv.w;
        float s = v[0]+v[1]+v[2]+v[3];
        float s2 = v[0]*v[0]+v[1]*v[1]+v[2]*v[2]+v[3]*v[3];
        #pragma unroll
        for (int off=16; off>0; off>>=1) {
            s  += __shfl_xor_sync(0xffffffffu, s,  off);
            s2 += __shfl_xor_sync(0xffffffffu, s2, off);
        }
        float mean = s * (1.f/128.f);
        float var  = s2 * (1.f/128.f) - mean*mean;
        float rs   = rsqrtf(var + 1e-5f);
        float4 o;
        o.x = (v[0]-mean)*rs*gg[0] + lb[0];
        o.y = (v[1]-mean)*rs*gg[1] + lb[1];
        o.z = (v[2]-mean)*rs*gg[2] + lb[2];
        o.w = (v[3]-mean)*rs*gg[3] + lb[3];
        if (mode == 0) {
            *(float4*)(out + (size_t)r*128 + tn*4) = o;
        } else {
            if (r < M1R) {
                *(float4*)(hout + (size_t)r*128 + tn*4) = o;
            } else {
                int rr = r - M1R;
                int t  = rr % NT2;
                if (t == 0) continue;
                int b  = rr / NT2;
                *(float4*)(dlast + ((size_t)b*NL + t - 1)*128 + tn*4) = o;
            }
        }
    }
}

// ---------------- masked per-channel attention (mTA) ----------------
// block: 128 threads; 64 q rows (2 threads/q, key halves), merged main+cls
__global__ void mta_kernel(const float* __restrict__ Qmain, const float* __restrict__ Qcls,
                           const float* __restrict__ K, const float* __restrict__ X,
                           float* __restrict__ o32main, float* __restrict__ o32cls)
{
    const int bh = blockIdx.y, b = bh >> 1, h = bh & 1;
    const bool cls = blockIdx.x >= 8;
    const int tile = cls ? (blockIdx.x - 8) : blockIdx.x;
    const float* Q = cls ? Qcls : Qmain;
    const int qStride = cls ? 0 : NL*128;
    const int Lq = cls ? 128 : NL;
    float* o32 = cls ? o32cls : o32main;

    const int tid = threadIdx.x, lane = tid & 31, warp = tid >> 5;
    const int qi = tile*64 + warp*16 + (lane & 15);
    const int half = lane >> 4;
    __shared__ float sK[2][32][64];
    __shared__ float sX[2][32][16];

    float4 qreg[16];
    const float* qp = Q + (size_t)b*qStride + (size_t)qi*128 + h*64;
    #pragma unroll
    for (int i=0;i<16;i++) qreg[i] = *(const float4*)(qp + i*4);

    float m = -1e30f;
    float den[8], num[8];
    #pragma unroll
    for (int c=0;c<8;c++){ den[c]=0.f; num[c]=0.f; }

    for (int c=0;c<8;c++) {             // 8 chunks of 32 keys per half
        __syncthreads();
        #pragma unroll
        for (int u=0;u<8;u++) {
            int e = (tid*8+u)*4;
            int hh = e>>11, kk = (e>>6)&31, d = e&63;
            int kglob = hh*256 + c*32 + kk;
            *(float4*)&sK[hh][kk][d] =
                *(const float4*)(K + ((size_t)b*NL + kglob)*128 + h*64 + d);
        }
        #pragma unroll
        for (int u=0;u<2;u++) {
            int e = (tid*2+u)*4;
            int hh = e>>9, kk = (e>>4)&31, d = e&15;
            int kglob = hh*256 + c*32 + kk;
            *(float4*)&sX[hh][kk][d] =
                *(const float4*)(X + ((size_t)b*NL + kglob)*16 + d);
        }
        __syncthreads();
        for (int kk=0;kk<32;kk++) {
            const float4* kr = (const float4*)sK[half][kk];
            float4 a4 = make_float4(0.f,0.f,0.f,0.f);
            #pragma unroll
            for (int i=0;i<16;i++) {
                float4 kv = kr[i];
                a4.x = fmaf(kv.x, qreg[i].x, a4.x);
                a4.y = fmaf(kv.y, qreg[i].y, a4.y);
                a4.z = fmaf(kv.z, qreg[i].z, a4.z);
                a4.w = fmaf(kv.w, qreg[i].w, a4.w);
            }
            float s = ((a4.x+a4.y)+(a4.z+a4.w))*0.125f;
            if (s > m) {
                float f = fexp(m - s);
                #pragma unroll
                for (int cc=0;cc<8;cc++){ den[cc]*=f; num[cc]*=f; }
                m = s;
            }
            float e = fexp(s - m);
            const float* xr = sX[half][kk];
            #pragma unroll
            for (int cc=0;cc<8;cc++) {
                float t = e * xr[8+cc];
                den[cc] += t;
                num[cc] = fmaf(t, xr[cc], num[cc]);
            }
        }
    }
    // merge the two key-halves (partner = lane ^ 16)
    float m2 = __shfl_xor_sync(0xffffffffu, m, 16);
    float Mx = fmaxf(m, m2);
    float f1 = fexp(m - Mx), f2 = fexp(m2 - Mx);
    #pragma unroll
    for (int cc=0;cc<8;cc++) {
        float d2 = __shfl_xor_sync(0xffffffffu, den[cc], 16);
        float n2 = __shfl_xor_sync(0xffffffffu, num[cc], 16);
        den[cc] = den[cc]*f1 + d2*f2;
        num[cc] = num[cc]*f1 + n2*f2;
    }
    if (half == 0) {
        float res[16];
        #pragma unroll
        for (int cc=0;cc<8;cc++) {
            bool ok = den[cc] > 0.f;
            res[cc]   = ok ? num[cc]/den[cc] : 0.f;
            res[8+cc] = ok ? 1.f : 0.f;
        }
        float* dst = o32 + ((size_t)b*Lq + qi)*32 + h*16;
        #pragma unroll
        for (int i=0;i<4;i++)
            *(float4*)(dst + i*4) = make_float4(res[i*4],res[i*4+1],res[i*4+2],res[i*4+3]);
    }
}

// ---------------- 32->128 projection into merged X + cls-row fill (16 rows/block) ----
__global__ void proj32_kernel(const float* __restrict__ Am, const float* __restrict__ Ac,
                              const float* __restrict__ W, const float* __restrict__ bias,
                              const float* __restrict__ pos, const float* __restrict__ cls_emb)
{
    if (blockIdx.x == 320) {     // cls token rows for both parts
        for (int i = threadIdx.x; i < 1024; i += 256) {
            int b = i >> 7, j = i & 127;
            float cv = cls_emb[j];
            g_X[((size_t)b*NT1)*128 + j] = cv;
            g_X[((size_t)M1R + (size_t)b*NT2)*128 + j] = cv + pos[j];
        }
        return;
    }
    __shared__ float sW[32*128];
    __shared__ float sA[16*32];
    const bool cls = blockIdx.x >= 256;
    const float* A = cls ? Ac : Am;
    const int Lq = cls ? 128 : NL;
    const int r0 = (cls ? (blockIdx.x - 256) : blockIdx.x) * 16;
    for (int i = threadIdx.x; i < 4096; i += 256) sW[i] = W[i];
    for (int i = threadIdx.x; i < 512; i += 256)
        sA[i] = A[(size_t)(r0 + (i >> 5))*32 + (i & 31)];
    __syncthreads();
    #pragma unroll
    for (int u=0;u<8;u++) {
        int oi = threadIdx.x + u*256;
        int lr = oi >> 7, col = oi & 127;
        int r = r0 + lr;
        float acc = bias[col];
        #pragma unroll
        for (int k=0;k<32;k++) acc = fmaf(sA[lr*32+k], sW[k*128+col], acc);
        int bb = r / Lq, q = r % Lq;
        size_t row;
        if (cls) row = (size_t)bb*NT1 + 1 + q;
        else   { row = (size_t)M1R + (size_t)bb*NT2 + 1 + q; acc += pos[(size_t)(1+q)*128 + col]; }
        g_X[row*128 + col] = acc;
    }
}

// ---------------- transformer-block attention (flash style), merged T1+T2 ----------------
// 128 threads; 64 q/block, 2 threads/q (key halves)
__global__ void tattn_kernel()
{
    const int y = blockIdx.y;
    const int part = y >> 4;              // 0: T1 block, 1: T2 block
    const int bh = y & 15, b = bh >> 1, h = bh & 1;
    const int T = part ? NT2 : NT1;
    const int base = part ? (M1R + b*NT2) : (b*NT1);
    if (blockIdx.x * 64 >= T) return;

    const int tid = threadIdx.x, lane = tid & 31, warp = tid >> 5;
    const int qi = blockIdx.x*64 + warp*16 + (lane & 15);
    const int half = lane >> 4;
    __shared__ float sK[2][32][64];
    __shared__ float sV[2][32][64];

    float4 qreg[16];
    if (qi < T) {
        const float* qp = g_Q + ((size_t)base + qi)*128 + h*64;
        #pragma unroll
        for (int i=0;i<16;i++) qreg[i] = *(const float4*)(qp + i*4);
    } else {
        #pragma unroll
        for (int i=0;i<16;i++) qreg[i] = make_float4(0.f,0.f,0.f,0.f);
    }
    float m = -1e30f, l = 0.f;
    float o[64];
    #pragma unroll
    for (int d=0;d<64;d++) o[d]=0.f;

    const int half0 = (T + 1) >> 1;
    const int kbase = half ? half0 : 0;
    const int kend  = half ? T : half0;
    const int hl1 = T - half0;
    const int nch = (((half0 > hl1) ? half0 : hl1) + 31) >> 5;

    for (int c=0;c<nch;c++) {
        __syncthreads();
        #pragma unroll
        for (int u=0;u<16;u++) {
            int e = (tid*16 + u)*4;
            int isV = e >> 12;
            int e2 = e & 4095;
            int hh = e2 >> 11, kk = (e2 >> 6) & 31, d = e2 & 63;
            int kglob = (hh ? half0 : 0) + c*32 + kk;
            int lim = hh ? T : half0;
            float4 v = make_float4(0.f,0.f,0.f,0.f);
            if (kglob < lim) {
                const float* src = (isV ? g_V : g_K) + ((size_t)base + kglob)*128 + h*64 + d;
                v = *(const float4*)src;
            }
            float* dst = isV ? &sV[hh][kk][d] : &sK[hh][kk][d];
            *(float4*)dst = v;
        }
        __syncthreads();
        const int k0 = kbase + c*32;
        for (int kk=0;kk<32;kk++) {
            const float4* kr = (const float4*)sK[half][kk];
            float4 a4 = make_float4(0.f,0.f,0.f,0.f);
            #pragma unroll
            for (int i=0;i<16;i++) {
                float4 kv = kr[i];
                a4.x = fmaf(kv.x, qreg[i].x, a4.x);
                a4.y = fmaf(kv.y, qreg[i].y, a4.y);
                a4.z = fmaf(kv.z, qreg[i].z, a4.z);
                a4.w = fmaf(kv.w, qreg[i].w, a4.w);
            }
            float s = ((a4.x+a4.y)+(a4.z+a4.w))*0.125f;
            if (k0 + kk < kend) {
                if (s > m) {
                    float f = fexp(m - s);
                    l *= f;
                    #pragma unroll
                    for (int d=0;d<64;d++) o[d]*=f;
                    m = s;
                }
                float e = fexp(s - m);
                l += e;
                const float4* vr = (const float4*)sV[half][kk];
                #pragma unroll
                for (int i=0;i<16;i++) {
                    float4 vv = vr[i];
                    o[i*4+0] = fmaf(e, vv.x, o[i*4+0]);
                    o[i*4+1] = fmaf(e, vv.y, o[i*4+1]);
                    o[i*4+2] = fmaf(e, vv.z, o[i*4+2]);
                    o[i*4+3] = fmaf(e, vv.w, o[i*4+3]);
                }
            }
        }
    }
    // merge halves
    float m2 = __shfl_xor_sync(0xffffffffu, m, 16);
    float Mx = fmaxf(m, m2);
    float f1 = fexp(m - Mx), f2 = fexp(m2 - Mx);
    float l2 = __shfl_xor_sync(0xffffffffu, l, 16);
    l = l*f1 + l2*f2;
    #pragma unroll
    for (int d=0;d<64;d++) {
        float o2 = __shfl_xor_sync(0xffffffffu, o[d], 16);
        o[d] = o[d]*f1 + o2*f2;
    }
    if (half == 0 && qi < T) {
        float inv = 1.0f / l;
        float* dst = g_AO + ((size_t)base + qi)*128 + h*64;
        #pragma unroll
        for (int i=0;i<16;i++)
            *(float4*)(dst + i*4) = make_float4(o[i*4]*inv, o[i*4+1]*inv, o[i*4+2]*inv, o[i*4+3]*inv);
    }
}

// ---------------- cls pooling ----------------
__global__ void pool_kernel(const float* __restrict__ pW,
                            const float* __restrict__ pb, float* __restrict__ dout)
{
    int b = blockIdx.x, j = threadIdx.x;
    __shared__ float s[128];
    s[j] = g_hout[((size_t)b*NT1)*128 + j];
    __syncthreads();
    float acc = pb[j];
    #pragma unroll
    for (int k=0;k<128;k++) acc = fmaf(s[k], pW[k*128 + j], acc);
    dout[b*128 + j] = tanhf(acc);
}

// ---------------- launch ----------------
extern "C" void kernel_launch(void* const* d_in, const int* in_sizes, int n_in,
                              void* d_out, int out_size)
{
    (void)in_sizes; (void)n_in; (void)out_size;
    const float* x       = (const float*)d_in[0];
    const float* ts      = (const float*)d_in[1];
    const float* w_per   = (const float*)d_in[2];
    const float* b_per   = (const float*)d_in[3];
    const float* w_lin   = (const float*)d_in[4];
    const float* b_lin   = (const float*)d_in[5];
    const float* Wq_t    = (const float*)d_in[6];
    const float* bq_t    = (const float*)d_in[7];
    const float* Wk_t    = (const float*)d_in[8];
    const float* bk_t    = (const float*)d_in[9];
    const float* Wo_t    = (const float*)d_in[10];
    const float* bo_t    = (const float*)d_in[11];
    const float* pos_emb = (const float*)d_in[12];
    const float* cls_emb = (const float*)d_in[13];
    const float* tWq = (const float*)d_in[14];
    const float* tbq = (const float*)d_in[15];
    const float* tWk = (const float*)d_in[16];
    const float* tbk = (const float*)d_in[17];
    const float* tWv = (const float*)d_in[18];
    const float* tbv = (const float*)d_in[19];
    const float* tWo = (const float*)d_in[20];
    const float* tbo = (const float*)d_in[21];
    const float* ln1_g = (const float*)d_in[22];
    const float* ln1_b = (const float*)d_in[23];
    const float* fW1 = (const float*)d_in[24];
    const float* fb1 = (const float*)d_in[25];
    const float* fW2 = (const float*)d_in[26];
    const float* fb2 = (const float*)d_in[27];
    const float* ln2_g = (const float*)d_in[28];
    const float* ln2_b = (const float*)d_in[29];
    const float* pW  = (const float*)d_in[30];
    const float* pb  = (const float*)d_in[31];
    float* dout = (float*)d_out;

    float *Qb, *Kb, *Qc, *o32a, *o32c, *X2, *AO, *F, *hout;
    cudaGetSymbolAddress((void**)&Qb,   g_Qb);
    cudaGetSymbolAddress((void**)&Kb,   g_Kb);
    cudaGetSymbolAddress((void**)&Qc,   g_Qc);
    cudaGetSymbolAddress((void**)&o32a, g_o32a);
    cudaGetSymbolAddress((void**)&o32c, g_o32c);
    cudaGetSymbolAddress((void**)&X2,   g_X2);
    cudaGetSymbolAddress((void**)&AO,   g_AO);
    cudaGetSymbolAddress((void**)&F,    g_F);
    cudaGetSymbolAddress((void**)&hout, g_hout);
    float* Xm; cudaGetSymbolAddress((void**)&Xm, g_X);

    // 1. time embeddings
    emb_kernel<<<NB*NL + 128, 128>>>(ts, w_per, b_per, w_lin, b_lin);

    // 2. K/Q projections (3 GEMMs in one launch)
    kq_gemm_kernel<<<dim3(64, 2, 3), 256>>>(Wq_t, bq_t, Wk_t, bk_t);

    // 3. masked channel attention (main + cls in one launch)
    mta_kernel<<<dim3(10, NB*2), 128>>>(Qb, Qc, Kb, x, o32a, o32c);

    // 4. build merged tblock input (includes cls-row fill)
    proj32_kernel<<<321, 256>>>(o32a, o32c, Wo_t, bo_t, pos_emb, cls_emb);

    // 5. merged tblock (both T=129 and T=513 at once, same weights)
    qkv_gemm_kernel<<<dim3((MTR+63)/64, 2, 3), 256>>>(tWq, tbq, tWk, tbk, tWv, tbv);
    tattn_kernel<<<dim3((NT2+63)/64, 32), 128>>>();
    gemm_ln_kernel<<<(MTR+31)/32, 256>>>(AO, tWo, tbo, Xm, ln1_g, ln1_b, X2, nullptr, nullptr, 0);
    gemm_kernel<<<dim3((MTR+63)/64, 2), 256>>>(X2, fW1, fb1, F, MTR, 1);
    gemm_ln_kernel<<<(MTR+31)/32, 256>>>(F, fW2, fb2, X2, ln2_g, ln2_b, nullptr, dout + 1024, hout, 1);

    // 6. cls pooling -> dout[0:1024]
    pool_kernel<<<NB, 128>>>(pW, pb, dout);
}

// round 7
// speedup vs baseline: 1.2846x; 1.0300x over previous
#include <cuda_runtime.h>
#include <math.h>

#define NB 8
#define NL 512
#define NE 128
#define NT1 129
#define NT2 513
#define M1R (NB*NT1)        // 1032
#define M2R (NB*NT2)        // 4104
#define MTR (M1R+M2R)       // 5136

// ---------------- device scratch ----------------
__device__ float g_Qb   [NB*NL*NE];
__device__ float g_Kb   [NB*NL*NE];
__device__ float g_Qc   [128*NE];
__device__ float g_o32a [NB*NL*32];
__device__ float g_o32c [NB*128*32];
__device__ float g_X    [MTR*128];
__device__ float g_Q    [MTR*128];
__device__ float g_K    [MTR*128];
__device__ float g_V    [MTR*128];
__device__ float g_X2   [MTR*128];
__device__ float g_hout [M1R*128];

// ---------------- fast exp on FMA/ALU pipes (args <= 0) ----------------
__device__ __forceinline__ float fexp(float x)
{
    x = fmaxf(x, -80.0f);
    float t  = x * 1.4426950408889634f;
    float kf = t + 12582912.0f;
    int   k  = __float_as_int(kf) - 0x4B400000;
    float f  = t - (kf - 12582912.0f);
    float p  = 1.3333558e-3f;
    p = fmaf(p, f, 9.6181291e-3f);
    p = fmaf(p, f, 5.5504109e-2f);
    p = fmaf(p, f, 2.4022651e-1f);
    p = fmaf(p, f, 6.9314718e-1f);
    p = fmaf(p, f, 1.0f);
    return __int_as_float(__float_as_int(p) + (k << 23));
}

// ---------------- K/Q projections with INLINE time-embedding generation ----------------
// z=0: Kb = emb(ts)@Wk, z=1: Qb = emb(ts)@Wq, z=2: Qc = emb(cls_t)@Wq
__global__ void kq_gemm_kernel(const float* __restrict__ ts,
                               const float* __restrict__ w_per, const float* __restrict__ b_per,
                               const float* __restrict__ w_lin, const float* __restrict__ b_lin,
                               const float* __restrict__ Wq, const float* __restrict__ bq,
                               const float* __restrict__ Wk, const float* __restrict__ bk)
{
    const int z = blockIdx.z;
    const float *W, *bias; float* C; int M;
    if (z == 0)      { W=Wk; bias=bk; C=g_Kb; M=NB*NL; }
    else if (z == 1) { W=Wq; bias=bq; C=g_Qb; M=NB*NL; }
    else             { W=Wq; bias=bq; C=g_Qc; M=128;  }
    if (blockIdx.x*64 >= M) return;

    __shared__ float As[16][64];
    __shared__ float Ws[16][64];
    const int tid = threadIdx.x;
    const int tn = tid & 15, tm = tid >> 4;
    const int m0 = blockIdx.x * 64, n0 = blockIdx.y * 64;
    float acc[4][4];
    #pragma unroll
    for (int i=0;i<4;i++)
        #pragma unroll
        for (int j=0;j<4;j++) acc[i][j] = 0.f;

    const int la  = tid * 4;
    const int lar = la >> 4, lac = la & 15;
    const int lwr = la >> 6, lwc = la & 63;

    const float wl = w_lin[0], bl = b_lin[0];
    const int gm = m0 + lar;
    const float t = (z == 2) ? (float)gm * (1.0f/127.0f) : ts[gm];

    for (int kk = 0; kk < 128; kk += 16) {
        float av[4];
        #pragma unroll
        for (int u=0;u<4;u++) {
            int j = kk + lac + u;
            av[u] = (j == 0) ? fmaf(t, wl, bl)
                             : sinf(fmaf(t, w_per[j-1], b_per[j-1]));
        }
        float4 wv = *(const float4*)(W + (size_t)(kk+lwr)*128 + n0 + lwc);
        __syncthreads();
        As[lac+0][lar]=av[0]; As[lac+1][lar]=av[1]; As[lac+2][lar]=av[2]; As[lac+3][lar]=av[3];
        *(float4*)&Ws[lwr][lwc] = wv;
        __syncthreads();
        #pragma unroll
        for (int k=0;k<16;k++) {
            float a[4], b[4];
            *(float4*)a = *(const float4*)&As[k][tm*4];
            *(float4*)b = *(const float4*)&Ws[k][tn*4];
            #pragma unroll
            for (int i=0;i<4;i++)
                #pragma unroll
                for (int j=0;j<4;j++) acc[i][j] = fmaf(a[i], b[j], acc[i][j]);
        }
    }
    float4 bv4 = *(const float4*)(bias + n0 + tn*4);
    float bb[4] = {bv4.x, bv4.y, bv4.z, bv4.w};
    #pragma unroll
    for (int i=0;i<4;i++) {
        float4 o;
        o.x = acc[i][0]+bb[0]; o.y = acc[i][1]+bb[1];
        o.z = acc[i][2]+bb[2]; o.w = acc[i][3]+bb[3];
        *(float4*)(C + (size_t)(m0 + tm*4 + i)*128 + n0 + tn*4) = o;
    }
}

// ---------------- 64x64-tile SGEMM (QKV of merged tblock rows) ----------------
__global__ void qkv_gemm_kernel(const float* __restrict__ Wq, const float* __restrict__ bq,
                                const float* __restrict__ Wk, const float* __restrict__ bk,
                                const float* __restrict__ Wv, const float* __restrict__ bv)
{
    const float *W, *bias; float* C;
    if (blockIdx.z == 0)      { W=Wq; bias=bq; C=g_Q; }
    else if (blockIdx.z == 1) { W=Wk; bias=bk; C=g_K; }
    else                      { W=Wv; bias=bv; C=g_V; }

    __shared__ float As[16][64];
    __shared__ float Ws[16][64];
    const int tid = threadIdx.x;
    const int tn = tid & 15, tm = tid >> 4;
    const int m0 = blockIdx.x * 64, n0 = blockIdx.y * 64;
    float acc[4][4];
    #pragma unroll
    for (int i=0;i<4;i++)
        #pragma unroll
        for (int j=0;j<4;j++) acc[i][j] = 0.f;

    const int la  = tid * 4;
    const int lar = la >> 4, lac = la & 15;
    const int lwr = la >> 6, lwc = la & 63;

    for (int kk = 0; kk < 128; kk += 16) {
        float4 av = make_float4(0.f,0.f,0.f,0.f);
        int gm = m0 + lar;
        if (gm < MTR) av = *(const float4*)(g_X + (size_t)gm*128 + kk + lac);
        float4 wv = *(const float4*)(W + (size_t)(kk+lwr)*128 + n0 + lwc);
        __syncthreads();
        As[lac+0][lar]=av.x; As[lac+1][lar]=av.y; As[lac+2][lar]=av.z; As[lac+3][lar]=av.w;
        *(float4*)&Ws[lwr][lwc] = wv;
        __syncthreads();
        #pragma unroll
        for (int k=0;k<16;k++) {
            float a[4], b[4];
            *(float4*)a = *(const float4*)&As[k][tm*4];
            *(float4*)b = *(const float4*)&Ws[k][tn*4];
            #pragma unroll
            for (int i=0;i<4;i++)
                #pragma unroll
                for (int j=0;j<4;j++) acc[i][j] = fmaf(a[i], b[j], acc[i][j]);
        }
    }
    float4 bv4 = *(const float4*)(bias + n0 + tn*4);
    float bb[4] = {bv4.x, bv4.y, bv4.z, bv4.w};
    #pragma unroll
    for (int i=0;i<4;i++) {
        int gm = m0 + tm*4 + i;
        if (gm < MTR) {
            float4 o;
            o.x = acc[i][0]+bb[0]; o.y = acc[i][1]+bb[1];
            o.z = acc[i][2]+bb[2]; o.w = acc[i][3]+bb[3];
            *(float4*)(C + (size_t)gm*128 + n0 + tn*4) = o;
        }
    }
}

// ---------------- masked per-channel attention (mTA) ----------------
__global__ void mta_kernel(const float* __restrict__ Qmain, const float* __restrict__ Qcls,
                           const float* __restrict__ K, const float* __restrict__ X,
                           float* __restrict__ o32main, float* __restrict__ o32cls)
{
    const int bh = blockIdx.y, b = bh >> 1, h = bh & 1;
    const bool cls = blockIdx.x >= 8;
    const int tile = cls ? (blockIdx.x - 8) : blockIdx.x;
    const float* Q = cls ? Qcls : Qmain;
    const int qStride = cls ? 0 : NL*128;
    const int Lq = cls ? 128 : NL;
    float* o32 = cls ? o32cls : o32main;

    const int tid = threadIdx.x, lane = tid & 31, warp = tid >> 5;
    const int qi = tile*64 + warp*16 + (lane & 15);
    const int half = lane >> 4;
    __shared__ float sK[2][32][64];
    __shared__ float sX[2][32][16];

    float4 qreg[16];
    const float* qp = Q + (size_t)b*qStride + (size_t)qi*128 + h*64;
    #pragma unroll
    for (int i=0;i<16;i++) qreg[i] = *(const float4*)(qp + i*4);

    float m = -1e30f;
    float den[8], num[8];
    #pragma unroll
    for (int c=0;c<8;c++){ den[c]=0.f; num[c]=0.f; }

    for (int c=0;c<8;c++) {
        __syncthreads();
        #pragma unroll
        for (int u=0;u<8;u++) {
            int e = (tid*8+u)*4;
            int hh = e>>11, kk = (e>>6)&31, d = e&63;
            int kglob = hh*256 + c*32 + kk;
            *(float4*)&sK[hh][kk][d] =
                *(const float4*)(K + ((size_t)b*NL + kglob)*128 + h*64 + d);
        }
        #pragma unroll
        for (int u=0;u<2;u++) {
            int e = (tid*2+u)*4;
            int hh = e>>9, kk = (e>>4)&31, d = e&15;
            int kglob = hh*256 + c*32 + kk;
            *(float4*)&sX[hh][kk][d] =
                *(const float4*)(X + ((size_t)b*NL + kglob)*16 + d);
        }
        __syncthreads();
        for (int kk=0;kk<32;kk++) {
            const float4* kr = (const float4*)sK[half][kk];
            float4 a4 = make_float4(0.f,0.f,0.f,0.f);
            #pragma unroll
            for (int i=0;i<16;i++) {
                float4 kv = kr[i];
                a4.x = fmaf(kv.x, qreg[i].x, a4.x);
                a4.y = fmaf(kv.y, qreg[i].y, a4.y);
                a4.z = fmaf(kv.z, qreg[i].z, a4.z);
                a4.w = fmaf(kv.w, qreg[i].w, a4.w);
            }
            float s = ((a4.x+a4.y)+(a4.z+a4.w))*0.125f;
            if (s > m) {
                float f = fexp(m - s);
                #pragma unroll
                for (int cc=0;cc<8;cc++){ den[cc]*=f; num[cc]*=f; }
                m = s;
            }
            float e = fexp(s - m);
            const float* xr = sX[half][kk];
            #pragma unroll
            for (int cc=0;cc<8;cc++) {
                float t = e * xr[8+cc];
                den[cc] += t;
                num[cc] = fmaf(t, xr[cc], num[cc]);
            }
        }
    }
    float m2 = __shfl_xor_sync(0xffffffffu, m, 16);
    float Mx = fmaxf(m, m2);
    float f1 = fexp(m - Mx), f2 = fexp(m2 - Mx);
    #pragma unroll
    for (int cc=0;cc<8;cc++) {
        float d2 = __shfl_xor_sync(0xffffffffu, den[cc], 16);
        float n2 = __shfl_xor_sync(0xffffffffu, num[cc], 16);
        den[cc] = den[cc]*f1 + d2*f2;
        num[cc] = num[cc]*f1 + n2*f2;
    }
    if (half == 0) {
        float res[16];
        #pragma unroll
        for (int cc=0;cc<8;cc++) {
            bool ok = den[cc] > 0.f;
            res[cc]   = ok ? num[cc]/den[cc] : 0.f;
            res[8+cc] = ok ? 1.f : 0.f;
        }
        float* dst = o32 + ((size_t)b*Lq + qi)*32 + h*16;
        #pragma unroll
        for (int i=0;i<4;i++)
            *(float4*)(dst + i*4) = make_float4(res[i*4],res[i*4+1],res[i*4+2],res[i*4+3]);
    }
}

// ---------------- 32->128 projection into merged X + cls-row fill ----------------
__global__ void proj32_kernel(const float* __restrict__ Am, const float* __restrict__ Ac,
                              const float* __restrict__ W, const float* __restrict__ bias,
                              const float* __restrict__ pos, const float* __restrict__ cls_emb)
{
    if (blockIdx.x == 320) {
        for (int i = threadIdx.x; i < 1024; i += 256) {
            int b = i >> 7, j = i & 127;
            float cv = cls_emb[j];
            g_X[((size_t)b*NT1)*128 + j] = cv;
            g_X[((size_t)M1R + (size_t)b*NT2)*128 + j] = cv + pos[j];
        }
        return;
    }
    __shared__ float sW[32*128];
    __shared__ float sA[16*32];
    const bool cls = blockIdx.x >= 256;
    const float* A = cls ? Ac : Am;
    const int Lq = cls ? 128 : NL;
    const int r0 = (cls ? (blockIdx.x - 256) : blockIdx.x) * 16;
    for (int i = threadIdx.x; i < 4096; i += 256) sW[i] = W[i];
    for (int i = threadIdx.x; i < 512; i += 256)
        sA[i] = A[(size_t)(r0 + (i >> 5))*32 + (i & 31)];
    __syncthreads();
    #pragma unroll
    for (int u=0;u<8;u++) {
        int oi = threadIdx.x + u*256;
        int lr = oi >> 7, col = oi & 127;
        int r = r0 + lr;
        float acc = bias[col];
        #pragma unroll
        for (int k=0;k<32;k++) acc = fmaf(sA[lr*32+k], sW[k*128+col], acc);
        int bb = r / Lq, q = r % Lq;
        size_t row;
        if (cls) row = (size_t)bb*NT1 + 1 + q;
        else   { row = (size_t)M1R + (size_t)bb*NT2 + 1 + q; acc += pos[(size_t)(1+q)*128 + col]; }
        g_X[row*128 + col] = acc;
    }
}

// ---------------- FUSED tblock attention: flash attn (both heads) + @Wo + res + LN1 → X2 ----
// 256 threads. Dyn smem: sK 8192f | sV 8192f | sAOt 128*65f | Ws 2048f
__global__ void __launch_bounds__(256, 1) tattn_kernel(const float* __restrict__ tWo,
                                                       const float* __restrict__ tbo,
                                                       const float* __restrict__ lng,
                                                       const float* __restrict__ lnb)
{
    const int y = blockIdx.y;
    const int part = y >> 3;
    const int b = y & 7;
    const int T = part ? NT2 : NT1;
    const int base = part ? (M1R + b*NT2) : (b*NT1);
    if (blockIdx.x * 64 >= T) return;

    extern __shared__ float sm[];
    float* sK   = sm;                  // [head][half][32][64]
    float* sV   = sm + 8192;
    float* sAOt = sm + 16384;          // [128 dims][65] (padded)
    float* sWs  = sm + 16384 + 128*65; // [16][128]

    const int tid = threadIdx.x;
    const int head = tid >> 7;
    const int wt = tid & 127;
    const int lane = wt & 31, warp4 = wt >> 5;
    const int qi = blockIdx.x*64 + warp4*16 + (lane & 15);
    const int half = lane >> 4;

    float4 qreg[16];
    if (qi < T) {
        const float* qp = g_Q + ((size_t)base + qi)*128 + head*64;
        #pragma unroll
        for (int i=0;i<16;i++) qreg[i] = *(const float4*)(qp + i*4);
    } else {
        #pragma unroll
        for (int i=0;i<16;i++) qreg[i] = make_float4(0.f,0.f,0.f,0.f);
    }
    float m = -1e30f, l = 0.f;
    float o[64];
    #pragma unroll
    for (int d=0;d<64;d++) o[d]=0.f;

    const int half0 = (T + 1) >> 1;
    const int kbase = half ? half0 : 0;
    const int kend  = half ? T : half0;
    const int hl1 = T - half0;
    const int nch = (((half0 > hl1) ? half0 : hl1) + 31) >> 5;

    for (int c=0;c<nch;c++) {
        __syncthreads();
        #pragma unroll
        for (int u=0;u<16;u++) {
            int e = (tid*16 + u)*4;            // 0..16383 floats
            int hd = e >> 13;
            int r  = e & 8191;
            int isV = r >> 12;
            int e3 = r & 4095;
            int hh = e3 >> 11, kk = (e3 >> 6) & 31, d = e3 & 63;
            int kglob = (hh ? half0 : 0) + c*32 + kk;
            int lim = hh ? T : half0;
            float4 v = make_float4(0.f,0.f,0.f,0.f);
            if (kglob < lim) {
                const float* src = (isV ? g_V : g_K) + ((size_t)base + kglob)*128 + hd*64 + d;
                v = *(const float4*)src;
            }
            float* dst = (isV ? sV : sK) + hd*4096 + e3;
            *(float4*)dst = v;
        }
        __syncthreads();
        const int k0 = kbase + c*32;
        const float* sKh = sK + head*4096 + half*2048;
        const float* sVh = sV + head*4096 + half*2048;
        for (int kk=0;kk<32;kk++) {
            const float4* kr = (const float4*)(sKh + kk*64);
            float4 a4 = make_float4(0.f,0.f,0.f,0.f);
            #pragma unroll
            for (int i=0;i<16;i++) {
                float4 kv = kr[i];
                a4.x = fmaf(kv.x, qreg[i].x, a4.x);
                a4.y = fmaf(kv.y, qreg[i].y, a4.y);
                a4.z = fmaf(kv.z, qreg[i].z, a4.z);
                a4.w = fmaf(kv.w, qreg[i].w, a4.w);
            }
            float s = ((a4.x+a4.y)+(a4.z+a4.w))*0.125f;
            if (k0 + kk < kend) {
                if (s > m) {
                    float f = fexp(m - s);
                    l *= f;
                    #pragma unroll
                    for (int d=0;d<64;d++) o[d]*=f;
                    m = s;
                }
                float e = fexp(s - m);
                l += e;
                const float4* vr = (const float4*)(sVh + kk*64);
                #pragma unroll
                for (int i=0;i<16;i++) {
                    float4 vv = vr[i];
                    o[i*4+0] = fmaf(e, vv.x, o[i*4+0]);
                    o[i*4+1] = fmaf(e, vv.y, o[i*4+1]);
                    o[i*4+2] = fmaf(e, vv.z, o[i*4+2]);
                    o[i*4+3] = fmaf(e, vv.w, o[i*4+3]);
                }
            }
        }
    }
    // merge halves
    float m2 = __shfl_xor_sync(0xffffffffu, m, 16);
    float Mx = fmaxf(m, m2);
    float f1 = fexp(m - Mx), f2 = fexp(m2 - Mx);
    float l2 = __shfl_xor_sync(0xffffffffu, l, 16);
    l = l*f1 + l2*f2;
    #pragma unroll
    for (int d=0;d<64;d++) {
        float o2 = __shfl_xor_sync(0xffffffffu, o[d], 16);
        o[d] = o[d]*f1 + o2*f2;
    }
    __syncthreads();      // sV/sK no longer needed; sAOt about to be written
    if (half == 0) {
        float inv = 1.0f / l;
        int qlocal = warp4*16 + (lane & 15);
        #pragma unroll
        for (int d=0;d<64;d++)
            sAOt[(head*64 + d)*65 + qlocal] = o[d]*inv;
    }
    __syncthreads();

    // ---- epilogue: AO(64x128) @ tWo + tbo + residual(g_X) → LN1 → g_X2 ----
    const int tn = tid & 31, tm = tid >> 5;   // warp tm handles rows tm*8..tm*8+7
    float acc[8][4];
    #pragma unroll
    for (int i=0;i<8;i++)
        #pragma unroll
        for (int j=0;j<4;j++) acc[i][j] = 0.f;

    for (int kk = 0; kk < 128; kk += 16) {
        int e0 = tid*8, e1 = tid*8 + 4;
        float4 w0 = *(const float4*)(tWo + (size_t)(kk + (e0>>7))*128 + (e0&127));
        float4 w1 = *(const float4*)(tWo + (size_t)(kk + (e1>>7))*128 + (e1&127));
        __syncthreads();
        *(float4*)&sWs[e0] = w0;
        *(float4*)&sWs[e1] = w1;
        __syncthreads();
        #pragma unroll
        for (int k=0;k<16;k++) {
            float bv[4];
            *(float4*)bv = *(const float4*)&sWs[k*128 + tn*4];
            const float* ar = &sAOt[(kk+k)*65 + tm*8];
            #pragma unroll
            for (int i=0;i<8;i++) {
                float a = ar[i];
                #pragma unroll
                for (int j=0;j<4;j++) acc[i][j] = fmaf(a, bv[j], acc[i][j]);
            }
        }
    }

    float4 bo4 = *(const float4*)(tbo + tn*4);
    float bo[4] = {bo4.x, bo4.y, bo4.z, bo4.w};
    float4 g4 = *(const float4*)(lng + tn*4);
    float4 be4 = *(const float4*)(lnb + tn*4);
    float gg[4] = {g4.x, g4.y, g4.z, g4.w};
    float lb[4] = {be4.x, be4.y, be4.z, be4.w};

    #pragma unroll
    for (int i=0;i<8;i++) {
        int qrow = blockIdx.x*64 + tm*8 + i;      // warp-uniform
        if (qrow >= T) continue;
        size_t gr = (size_t)base + qrow;
        float4 rv = *(const float4*)(g_X + gr*128 + tn*4);
        float v[4];
        v[0] = acc[i][0] + bo[0] + rv.x;
        v[1] = acc[i][1] + bo[1] + rv.y;
        v[2] = acc[i][2] + bo[2] + rv.z;
        v[3] = acc[i][3] + bo[3] + rv.w;
        float s = v[0]+v[1]+v[2]+v[3];
        float s2 = v[0]*v[0]+v[1]*v[1]+v[2]*v[2]+v[3]*v[3];
        #pragma unroll
        for (int off=16; off>0; off>>=1) {
            s  += __shfl_xor_sync(0xffffffffu, s,  off);
            s2 += __shfl_xor_sync(0xffffffffu, s2, off);
        }
        float mean = s * (1.f/128.f);
        float var  = s2 * (1.f/128.f) - mean*mean;
        float rs   = rsqrtf(var + 1e-5f);
        float4 ov;
        ov.x = (v[0]-mean)*rs*gg[0] + lb[0];
        ov.y = (v[1]-mean)*rs*gg[1] + lb[1];
        ov.z = (v[2]-mean)*rs*gg[2] + lb[2];
        ov.w = (v[3]-mean)*rs*gg[3] + lb[3];
        *(float4*)(g_X2 + gr*128 + tn*4) = ov;
    }
}

// ---------------- FUSED FFN: relu(X2@W1+b1)@W2+b2 + res + LN2 → hout / dlast ----------------
__global__ void ffn_kernel(const float* __restrict__ fW1, const float* __restrict__ fb1,
                           const float* __restrict__ fW2, const float* __restrict__ fb2,
                           const float* __restrict__ lng, const float* __restrict__ lnb,
                           float* __restrict__ dlast)
{
    __shared__ float As[16][32];
    __shared__ float Ws[16*128];
    __shared__ float sFt[128*33];     // transposed F, padded

    const int tid = threadIdx.x;
    const int tn = tid & 31, tm = tid >> 5;
    const int m0 = blockIdx.x * 32;
    const int lam = tid & 31, lak = (tid >> 5) * 2;

    // phase 1: F = relu(X2 @ W1 + b1)
    float acc[4][4];
    #pragma unroll
    for (int i=0;i<4;i++)
        #pragma unroll
        for (int j=0;j<4;j++) acc[i][j] = 0.f;

    for (int kk = 0; kk < 128; kk += 16) {
        float2 av = make_float2(0.f,0.f);
        int gm = m0 + lam;
        if (gm < MTR) av = *(const float2*)(g_X2 + (size_t)gm*128 + kk + lak);
        int i0 = tid*4, i1 = tid*4 + 1024;
        float4 wv0 = *(const float4*)(fW1 + (size_t)(kk + (i0>>7))*128 + (i0&127));
        float4 wv1 = *(const float4*)(fW1 + (size_t)(kk + (i1>>7))*128 + (i1&127));
        __syncthreads();
        As[lak][lam] = av.x; As[lak+1][lam] = av.y;
        *(float4*)&Ws[i0] = wv0;
        *(float4*)&Ws[i1] = wv1;
        __syncthreads();
        #pragma unroll
        for (int k=0;k<16;k++) {
            float a[4], b[4];
            *(float4*)a = *(const float4*)&As[k][tm*4];
            *(float4*)b = *(const float4*)&Ws[k*128 + tn*4];
            #pragma unroll
            for (int i=0;i<4;i++)
                #pragma unroll
                for (int j=0;j<4;j++) acc[i][j] = fmaf(a[i], b[j], acc[i][j]);
        }
    }
    {
        float4 b14 = *(const float4*)(fb1 + tn*4);
        float b1[4] = {b14.x, b14.y, b14.z, b14.w};
        __syncthreads();
        #pragma unroll
        for (int i=0;i<4;i++)
            #pragma unroll
            for (int j=0;j<4;j++)
                sFt[(tn*4+j)*33 + tm*4+i] = fmaxf(acc[i][j] + b1[j], 0.f);
    }

    // phase 2: out = F @ W2 + b2 + res → LN2
    #pragma unroll
    for (int i=0;i<4;i++)
        #pragma unroll
        for (int j=0;j<4;j++) acc[i][j] = 0.f;

    for (int kk = 0; kk < 128; kk += 16) {
        int i0 = tid*4, i1 = tid*4 + 1024;
        float4 wv0 = *(const float4*)(fW2 + (size_t)(kk + (i0>>7))*128 + (i0&127));
        float4 wv1 = *(const float4*)(fW2 + (size_t)(kk + (i1>>7))*128 + (i1&127));
        __syncthreads();
        *(float4*)&Ws[i0] = wv0;
        *(float4*)&Ws[i1] = wv1;
        __syncthreads();
        #pragma unroll
        for (int k=0;k<16;k++) {
            float b[4];
            *(float4*)b = *(const float4*)&Ws[k*128 + tn*4];
            const float* ar = &sFt[(kk+k)*33 + tm*4];
            #pragma unroll
            for (int i=0;i<4;i++) {
                float a = ar[i];
                #pragma unroll
                for (int j=0;j<4;j++) acc[i][j] = fmaf(a, b[j], acc[i][j]);
            }
        }
    }

    float4 bb4 = *(const float4*)(fb2 + tn*4);
    float bb[4] = {bb4.x, bb4.y, bb4.z, bb4.w};
    float4 g4 = *(const float4*)(lng + tn*4);
    float4 be4 = *(const float4*)(lnb + tn*4);
    float gg[4] = {g4.x, g4.y, g4.z, g4.w};
    float lb[4] = {be4.x, be4.y, be4.z, be4.w};

    #pragma unroll
    for (int i=0;i<4;i++) {
        int r = m0 + tm*4 + i;
        if (r >= MTR) continue;
        float4 rv = *(const float4*)(g_X2 + (size_t)r*128 + tn*4);
        float v[4];
        v[0] = acc[i][0] + bb[0] + rv.x;
        v[1] = acc[i][1] + bb[1] + rv.y;
        v[2] = acc[i][2] + bb[2] + rv.z;
        v[3] = acc[i][3] + bb[3] + rv.w;
        float s = v[0]+v[1]+v[2]+v[3];
        float s2 = v[0]*v[0]+v[1]*v[1]+v[2]*v[2]+v[3]*v[3];
        #pragma unroll
        for (int off=16; off>0; off>>=1) {
            s  += __shfl_xor_sync(0xffffffffu, s,  off);
            s2 += __shfl_xor_sync(0xffffffffu, s2, off);
        }
        float mean = s * (1.f/128.f);
        float var  = s2 * (1.f/128.f) - mean*mean;
        float rs   = rsqrtf(var + 1e-5f);
        float4 ov;
        ov.x = (v[0]-mean)*rs*gg[0] + lb[0];
        ov.y = (v[1]-mean)*rs*gg[1] + lb[1];
        ov.z = (v[2]-mean)*rs*gg[2] + lb[2];
        ov.w = (v[3]-mean)*rs*gg[3] + lb[3];
        if (r < M1R) {
            *(float4*)(g_hout + (size_t)r*128 + tn*4) = ov;
        } else {
            int rr = r - M1R;
            int t  = rr % NT2;
            if (t == 0) continue;
            int b  = rr / NT2;
            *(float4*)(dlast + ((size_t)b*NL + t - 1)*128 + tn*4) = ov;
        }
    }
}

// ---------------- cls pooling ----------------
__global__ void pool_kernel(const float* __restrict__ pW,
                            const float* __restrict__ pb, float* __restrict__ dout)
{
    int b = blockIdx.x, j = threadIdx.x;
    __shared__ float s[128];
    s[j] = g_hout[((size_t)b*NT1)*128 + j];
    __syncthreads();
    float acc = pb[j];
    #pragma unroll
    for (int k=0;k<128;k++) acc = fmaf(s[k], pW[k*128 + j], acc);
    dout[b*128 + j] = tanhf(acc);
}

// ---------------- launch ----------------
extern "C" void kernel_launch(void* const* d_in, const int* in_sizes, int n_in,
                              void* d_out, int out_size)
{
    (void)in_sizes; (void)n_in; (void)out_size;
    const float* x       = (const float*)d_in[0];
    const float* ts      = (const float*)d_in[1];
    const float* w_per   = (const float*)d_in[2];
    const float* b_per   = (const float*)d_in[3];
    const float* w_lin   = (const float*)d_in[4];
    const float* b_lin   = (const float*)d_in[5];
    const float* Wq_t    = (const float*)d_in[6];
    const float* bq_t    = (const float*)d_in[7];
    const float* Wk_t    = (const float*)d_in[8];
    const float* bk_t    = (const float*)d_in[9];
    const float* Wo_t    = (const float*)d_in[10];
    const float* bo_t    = (const float*)d_in[11];
    const float* pos_emb = (const float*)d_in[12];
    const float* cls_emb = (const float*)d_in[13];
    const float* tWq = (const float*)d_in[14];
    const float* tbq = (const float*)d_in[15];
    const float* tWk = (const float*)d_in[16];
    const float* tbk = (const float*)d_in[17];
    const float* tWv = (const float*)d_in[18];
    const float* tbv = (const float*)d_in[19];
    const float* tWo = (const float*)d_in[20];
    const float* tbo = (const float*)d_in[21];
    const float* ln1_g = (const float*)d_in[22];
    const float* ln1_b = (const float*)d_in[23];
    const float* fW1 = (const float*)d_in[24];
    const float* fb1 = (const float*)d_in[25];
    const float* fW2 = (const float*)d_in[26];
    const float* fb2 = (const float*)d_in[27];
    const float* ln2_g = (const float*)d_in[28];
    const float* ln2_b = (const float*)d_in[29];
    const float* pW  = (const float*)d_in[30];
    const float* pb  = (const float*)d_in[31];
    float* dout = (float*)d_out;

    float *Qb, *Kb, *Qc, *o32a, *o32c;
    cudaGetSymbolAddress((void**)&Qb,   g_Qb);
    cudaGetSymbolAddress((void**)&Kb,   g_Kb);
    cudaGetSymbolAddress((void**)&Qc,   g_Qc);
    cudaGetSymbolAddress((void**)&o32a, g_o32a);
    cudaGetSymbolAddress((void**)&o32c, g_o32c);

    const int TATTN_SMEM = (8192 + 8192 + 128*65 + 2048) * 4;   // 107008 B
    cudaFuncSetAttribute(tattn_kernel, cudaFuncAttributeMaxDynamicSharedMemorySize, TATTN_SMEM);

    // 1. K/Q projections with inline time-embedding
    kq_gemm_kernel<<<dim3(64, 2, 3), 256>>>(ts, w_per, b_per, w_lin, b_lin,
                                            Wq_t, bq_t, Wk_t, bk_t);

    // 2. masked channel attention (main + cls)
    mta_kernel<<<dim3(10, NB*2), 128>>>(Qb, Qc, Kb, x, o32a, o32c);

    // 3. build merged tblock input (incl. cls rows)
    proj32_kernel<<<321, 256>>>(o32a, o32c, Wo_t, bo_t, pos_emb, cls_emb);

    // 4. QKV
    qkv_gemm_kernel<<<dim3((MTR+63)/64, 2, 3), 256>>>(tWq, tbq, tWk, tbk, tWv, tbv);

    // 5. fused attention + Wo + residual + LN1 → X2
    tattn_kernel<<<dim3((NT2+63)/64, 16), 256, TATTN_SMEM>>>(tWo, tbo, ln1_g, ln1_b);

    // 6. fused FFN + residual + LN2 → hout / last_hidden
    ffn_kernel<<<(MTR+31)/32, 256>>>(fW1, fb1, fW2, fb2, ln2_g, ln2_b, dout + 1024);

    // 7. cls pooling
    pool_kernel<<<NB, 128>>>(pW, pb, dout);
}

// round 8
// speedup vs baseline: 1.3288x; 1.0344x over previous
#include <cuda_runtime.h>
#include <math.h>
#include <stdint.h>

#define NB 8
#define NL 512
#define NE 128
#define NT1 129
#define NT2 513
#define M1R (NB*NT1)        // 1032
#define M2R (NB*NT2)        // 4104
#define MTR (M1R+M2R)       // 5136

// ---------------- device scratch ----------------
__device__ float g_Qb   [NB*NL*NE];
__device__ float g_Kb   [NB*NL*NE];
__device__ float g_Qc   [128*NE];
__device__ float g_o32a [NB*NL*32];
__device__ float g_o32c [NB*128*32];
__device__ float g_X    [MTR*128];
__device__ float g_Q    [MTR*128];
__device__ float g_K    [MTR*128];
__device__ float g_V    [MTR*128];
__device__ float g_X2   [MTR*128];
__device__ float g_hout [M1R*128];

// ---------------- fast exp on FMA/ALU pipes (args <= 0) ----------------
__device__ __forceinline__ float fexp(float x)
{
    x = fmaxf(x, -80.0f);
    float t  = x * 1.4426950408889634f;
    float kf = t + 12582912.0f;
    int   k  = __float_as_int(kf) - 0x4B400000;
    float f  = t - (kf - 12582912.0f);
    float p  = 1.3333558e-3f;
    p = fmaf(p, f, 9.6181291e-3f);
    p = fmaf(p, f, 5.5504109e-2f);
    p = fmaf(p, f, 2.4022651e-1f);
    p = fmaf(p, f, 6.9314718e-1f);
    p = fmaf(p, f, 1.0f);
    return __int_as_float(__float_as_int(p) + (k << 23));
}

// ---------------- tf32 helpers ----------------
__device__ __forceinline__ float f2tf(float f)
{
    uint32_t r;
    asm("cvt.rna.tf32.f32 %0, %1;" : "=r"(r) : "f"(f));
    return __uint_as_float(r);
}

__device__ __forceinline__ void mma8(float* c, uint32_t a0, uint32_t a1, uint32_t a2, uint32_t a3,
                                     uint32_t b0, uint32_t b1)
{
    asm volatile("mma.sync.aligned.m16n8k8.row.col.f32.tf32.tf32.f32 "
                 "{%0,%1,%2,%3}, {%4,%5,%6,%7}, {%8,%9}, {%0,%1,%2,%3};"
                 : "+f"(c[0]), "+f"(c[1]), "+f"(c[2]), "+f"(c[3])
                 : "r"(a0), "r"(a1), "r"(a2), "r"(a3), "r"(b0), "r"(b1));
}

// 32x128 block tile, 8 warps (16 cols each). As pitch 36, Ws pitch 132. One K-chunk of 32.
__device__ __forceinline__ void mma_chunk(const float* As, const float* Ws,
                                          int n0w, int g, int tig, float acc[2][2][4])
{
    #pragma unroll
    for (int j=0;j<4;j++) {
        uint32_t a[2][4];
        #pragma unroll
        for (int mi=0;mi<2;mi++) {
            int rb = mi*16;
            a[mi][0] = __float_as_uint(As[(rb+g)*36   + j*8+tig]);
            a[mi][1] = __float_as_uint(As[(rb+g+8)*36 + j*8+tig]);
            a[mi][2] = __float_as_uint(As[(rb+g)*36   + j*8+tig+4]);
            a[mi][3] = __float_as_uint(As[(rb+g+8)*36 + j*8+tig+4]);
        }
        #pragma unroll
        for (int ni=0;ni<2;ni++) {
            int cb = n0w + ni*8 + g;
            uint32_t b0 = __float_as_uint(Ws[(j*8+tig)*132   + cb]);
            uint32_t b1 = __float_as_uint(Ws[(j*8+tig+4)*132 + cb]);
            mma8(acc[0][ni], a[0][0],a[0][1],a[0][2],a[0][3], b0,b1);
            mma8(acc[1][ni], a[1][0],a[1][1],a[1][2],a[1][3], b0,b1);
        }
    }
}

// A-frag chunk reading directly from pitch-132 smem (phase-2 of FFN), cols kc..kc+31
__device__ __forceinline__ void mma_chunk_F(const float* F, int kc, const float* Ws,
                                            int n0w, int g, int tig, float acc[2][2][4])
{
    #pragma unroll
    for (int j=0;j<4;j++) {
        uint32_t a[2][4];
        #pragma unroll
        for (int mi=0;mi<2;mi++) {
            int rb = mi*16;
            a[mi][0] = __float_as_uint(F[(rb+g)*132   + kc + j*8+tig]);
            a[mi][1] = __float_as_uint(F[(rb+g+8)*132 + kc + j*8+tig]);
            a[mi][2] = __float_as_uint(F[(rb+g)*132   + kc + j*8+tig+4]);
            a[mi][3] = __float_as_uint(F[(rb+g+8)*132 + kc + j*8+tig+4]);
        }
        #pragma unroll
        for (int ni=0;ni<2;ni++) {
            int cb = n0w + ni*8 + g;
            uint32_t b0 = __float_as_uint(Ws[(j*8+tig)*132   + cb]);
            uint32_t b1 = __float_as_uint(Ws[(j*8+tig+4)*132 + cb]);
            mma8(acc[0][ni], a[0][0],a[0][1],a[0][2],a[0][3], b0,b1);
            mma8(acc[1][ni], a[1][0],a[1][1],a[1][2],a[1][3], b0,b1);
        }
    }
}

// stage W chunk (32x128) into Ws (pitch 132), tf32-converted
__device__ __forceinline__ void stage_W(float* Ws, const float* W, int kc, int tid)
{
    #pragma unroll
    for (int u=0;u<4;u++) {
        int e = tid*16 + u*4;
        int r = e >> 7, c = e & 127;
        float4 w4 = *(const float4*)(W + (size_t)(kc + r)*128 + c);
        *(float4*)&Ws[r*132 + c] =
            make_float4(f2tf(w4.x), f2tf(w4.y), f2tf(w4.z), f2tf(w4.w));
    }
}

// ---------------- K/Q projections (tf32 mma) with inline time-embedding ----------------
// z=0: Kb = emb(ts)@Wk, z=1: Qb = emb(ts)@Wq, z=2: Qc = emb(cls_t)@Wq
__global__ void __launch_bounds__(256) kq_gemm_kernel(
    const float* __restrict__ ts,
    const float* __restrict__ w_per, const float* __restrict__ b_per,
    const float* __restrict__ w_lin, const float* __restrict__ b_lin,
    const float* __restrict__ Wq, const float* __restrict__ bq,
    const float* __restrict__ Wk, const float* __restrict__ bk)
{
    const int z = blockIdx.z;
    const float *W, *bias; float* C; int M;
    if (z == 0)      { W=Wk; bias=bk; C=g_Kb; M=NB*NL; }
    else if (z == 1) { W=Wq; bias=bq; C=g_Qb; M=NB*NL; }
    else             { W=Wq; bias=bq; C=g_Qc; M=128;  }
    const int m0 = blockIdx.x * 32;
    if (m0 >= M) return;

    __shared__ float As[32*36];
    __shared__ float Ws[32*132];

    const int tid = threadIdx.x;
    const int lane = tid & 31, warp = tid >> 5;
    const int g = lane >> 2, tig = lane & 3;
    const int n0w = warp * 16;

    float acc[2][2][4];
    #pragma unroll
    for (int a=0;a<2;a++)
        #pragma unroll
        for (int b=0;b<2;b++)
            #pragma unroll
            for (int c=0;c<4;c++) acc[a][b][c] = 0.f;

    const float wl = w_lin[0], bl = b_lin[0];
    const int ar = (tid*4) >> 5;          // staging row 0..31
    const int ac = (tid*4) & 31;          // staging col base
    const int grow = m0 + ar;
    const float tval = (grow < M) ? ((z == 2) ? (float)grow*(1.0f/127.0f) : ts[grow]) : 0.f;

    for (int kc = 0; kc < 128; kc += 32) {
        __syncthreads();
        {   // A stage: generate embedding elements
            float v[4];
            #pragma unroll
            for (int u=0;u<4;u++) {
                int j = kc + ac + u;
                v[u] = (j == 0) ? fmaf(tval, wl, bl)
                                : sinf(fmaf(tval, w_per[j-1], b_per[j-1]));
            }
            *(float4*)&As[ar*36 + ac] =
                make_float4(f2tf(v[0]), f2tf(v[1]), f2tf(v[2]), f2tf(v[3]));
        }
        stage_W(Ws, W, kc, tid);
        __syncthreads();
        mma_chunk(As, Ws, n0w, g, tig, acc);
    }

    #pragma unroll
    for (int ni=0;ni<2;ni++) {
        int col = n0w + ni*8 + tig*2;
        float b0 = bias[col], b1v = bias[col+1];
        #pragma unroll
        for (int mi=0;mi<2;mi++) {
            int row = m0 + mi*16 + g;
            if (row < M)
                *(float2*)(C + (size_t)row*128 + col) =
                    make_float2(acc[mi][ni][0]+b0, acc[mi][ni][1]+b1v);
            if (row + 8 < M)
                *(float2*)(C + (size_t)(row+8)*128 + col) =
                    make_float2(acc[mi][ni][2]+b0, acc[mi][ni][3]+b1v);
        }
    }
}

// ---------------- QKV (tf32 mma) ----------------
__global__ void __launch_bounds__(256) qkv_gemm_kernel(
    const float* __restrict__ Wq, const float* __restrict__ bq,
    const float* __restrict__ Wk, const float* __restrict__ bk,
    const float* __restrict__ Wv, const float* __restrict__ bv)
{
    const float *W, *bias; float* C;
    if (blockIdx.z == 0)      { W=Wq; bias=bq; C=g_Q; }
    else if (blockIdx.z == 1) { W=Wk; bias=bk; C=g_K; }
    else                      { W=Wv; bias=bv; C=g_V; }
    const int m0 = blockIdx.x * 32;

    __shared__ float As[32*36];
    __shared__ float Ws[32*132];

    const int tid = threadIdx.x;
    const int lane = tid & 31, warp = tid >> 5;
    const int g = lane >> 2, tig = lane & 3;
    const int n0w = warp * 16;

    float acc[2][2][4];
    #pragma unroll
    for (int a=0;a<2;a++)
        #pragma unroll
        for (int b=0;b<2;b++)
            #pragma unroll
            for (int c=0;c<4;c++) acc[a][b][c] = 0.f;

    const int ar = (tid*4) >> 5;
    const int ac = (tid*4) & 31;
    const int grow = m0 + ar;

    for (int kc = 0; kc < 128; kc += 32) {
        __syncthreads();
        {
            float4 a4 = make_float4(0.f,0.f,0.f,0.f);
            if (grow < MTR) a4 = *(const float4*)(g_X + (size_t)grow*128 + kc + ac);
            *(float4*)&As[ar*36 + ac] =
                make_float4(f2tf(a4.x), f2tf(a4.y), f2tf(a4.z), f2tf(a4.w));
        }
        stage_W(Ws, W, kc, tid);
        __syncthreads();
        mma_chunk(As, Ws, n0w, g, tig, acc);
    }

    #pragma unroll
    for (int ni=0;ni<2;ni++) {
        int col = n0w + ni*8 + tig*2;
        float b0 = bias[col], b1v = bias[col+1];
        #pragma unroll
        for (int mi=0;mi<2;mi++) {
            int row = m0 + mi*16 + g;
            if (row < MTR)
                *(float2*)(C + (size_t)row*128 + col) =
                    make_float2(acc[mi][ni][0]+b0, acc[mi][ni][1]+b1v);
            if (row + 8 < MTR)
                *(float2*)(C + (size_t)(row+8)*128 + col) =
                    make_float2(acc[mi][ni][2]+b0, acc[mi][ni][3]+b1v);
        }
    }
}

// ---------------- masked per-channel attention (mTA) ----------------
__global__ void mta_kernel(const float* __restrict__ Qmain, const float* __restrict__ Qcls,
                           const float* __restrict__ K, const float* __restrict__ X,
                           float* __restrict__ o32main, float* __restrict__ o32cls)
{
    const int bh = blockIdx.y, b = bh >> 1, h = bh & 1;
    const bool cls = blockIdx.x >= 8;
    const int tile = cls ? (blockIdx.x - 8) : blockIdx.x;
    const float* Q = cls ? Qcls : Qmain;
    const int qStride = cls ? 0 : NL*128;
    const int Lq = cls ? 128 : NL;
    float* o32 = cls ? o32cls : o32main;

    const int tid = threadIdx.x, lane = tid & 31, warp = tid >> 5;
    const int qi = tile*64 + warp*16 + (lane & 15);
    const int half = lane >> 4;
    __shared__ float sK[2][32][64];
    __shared__ float sX[2][32][16];

    float4 qreg[16];
    const float* qp = Q + (size_t)b*qStride + (size_t)qi*128 + h*64;
    #pragma unroll
    for (int i=0;i<16;i++) qreg[i] = *(const float4*)(qp + i*4);

    float m = -1e30f;
    float den[8], num[8];
    #pragma unroll
    for (int c=0;c<8;c++){ den[c]=0.f; num[c]=0.f; }

    for (int c=0;c<8;c++) {
        __syncthreads();
        #pragma unroll
        for (int u=0;u<8;u++) {
            int e = (tid*8+u)*4;
            int hh = e>>11, kk = (e>>6)&31, d = e&63;
            int kglob = hh*256 + c*32 + kk;
            *(float4*)&sK[hh][kk][d] =
                *(const float4*)(K + ((size_t)b*NL + kglob)*128 + h*64 + d);
        }
        #pragma unroll
        for (int u=0;u<2;u++) {
            int e = (tid*2+u)*4;
            int hh = e>>9, kk = (e>>4)&31, d = e&15;
            int kglob = hh*256 + c*32 + kk;
            *(float4*)&sX[hh][kk][d] =
                *(const float4*)(X + ((size_t)b*NL + kglob)*16 + d);
        }
        __syncthreads();
        for (int kk=0;kk<32;kk++) {
            const float4* kr = (const float4*)sK[half][kk];
            float4 a4 = make_float4(0.f,0.f,0.f,0.f);
            #pragma unroll
            for (int i=0;i<16;i++) {
                float4 kv = kr[i];
                a4.x = fmaf(kv.x, qreg[i].x, a4.x);
                a4.y = fmaf(kv.y, qreg[i].y, a4.y);
                a4.z = fmaf(kv.z, qreg[i].z, a4.z);
                a4.w = fmaf(kv.w, qreg[i].w, a4.w);
            }
            float s = ((a4.x+a4.y)+(a4.z+a4.w))*0.125f;
            if (s > m) {
                float f = fexp(m - s);
                #pragma unroll
                for (int cc=0;cc<8;cc++){ den[cc]*=f; num[cc]*=f; }
                m = s;
            }
            float e = fexp(s - m);
            const float* xr = sX[half][kk];
            #pragma unroll
            for (int cc=0;cc<8;cc++) {
                float t = e * xr[8+cc];
                den[cc] += t;
                num[cc] = fmaf(t, xr[cc], num[cc]);
            }
        }
    }
    float m2 = __shfl_xor_sync(0xffffffffu, m, 16);
    float Mx = fmaxf(m, m2);
    float f1 = fexp(m - Mx), f2 = fexp(m2 - Mx);
    #pragma unroll
    for (int cc=0;cc<8;cc++) {
        float d2 = __shfl_xor_sync(0xffffffffu, den[cc], 16);
        float n2 = __shfl_xor_sync(0xffffffffu, num[cc], 16);
        den[cc] = den[cc]*f1 + d2*f2;
        num[cc] = num[cc]*f1 + n2*f2;
    }
    if (half == 0) {
        float res[16];
        #pragma unroll
        for (int cc=0;cc<8;cc++) {
            bool ok = den[cc] > 0.f;
            res[cc]   = ok ? num[cc]/den[cc] : 0.f;
            res[8+cc] = ok ? 1.f : 0.f;
        }
        float* dst = o32 + ((size_t)b*Lq + qi)*32 + h*16;
        #pragma unroll
        for (int i=0;i<4;i++)
            *(float4*)(dst + i*4) = make_float4(res[i*4],res[i*4+1],res[i*4+2],res[i*4+3]);
    }
}

// ---------------- 32->128 projection into merged X + cls-row fill ----------------
__global__ void proj32_kernel(const float* __restrict__ Am, const float* __restrict__ Ac,
                              const float* __restrict__ W, const float* __restrict__ bias,
                              const float* __restrict__ pos, const float* __restrict__ cls_emb)
{
    if (blockIdx.x == 320) {
        for (int i = threadIdx.x; i < 1024; i += 256) {
            int b = i >> 7, j = i & 127;
            float cv = cls_emb[j];
            g_X[((size_t)b*NT1)*128 + j] = cv;
            g_X[((size_t)M1R + (size_t)b*NT2)*128 + j] = cv + pos[j];
        }
        return;
    }
    __shared__ float sW[32*128];
    __shared__ float sA[16*32];
    const bool cls = blockIdx.x >= 256;
    const float* A = cls ? Ac : Am;
    const int Lq = cls ? 128 : NL;
    const int r0 = (cls ? (blockIdx.x - 256) : blockIdx.x) * 16;
    for (int i = threadIdx.x; i < 4096; i += 256) sW[i] = W[i];
    for (int i = threadIdx.x; i < 512; i += 256)
        sA[i] = A[(size_t)(r0 + (i >> 5))*32 + (i & 31)];
    __syncthreads();
    #pragma unroll
    for (int u=0;u<8;u++) {
        int oi = threadIdx.x + u*256;
        int lr = oi >> 7, col = oi & 127;
        int r = r0 + lr;
        float acc = bias[col];
        #pragma unroll
        for (int k=0;k<32;k++) acc = fmaf(sA[lr*32+k], sW[k*128+col], acc);
        int bb = r / Lq, q = r % Lq;
        size_t row;
        if (cls) row = (size_t)bb*NT1 + 1 + q;
        else   { row = (size_t)M1R + (size_t)bb*NT2 + 1 + q; acc += pos[(size_t)(1+q)*128 + col]; }
        g_X[row*128 + col] = acc;
    }
}

// ---------------- FUSED tblock attention: flash attn (both heads) + @Wo + res + LN1 → X2 ----
__global__ void __launch_bounds__(256, 1) tattn_kernel(const float* __restrict__ tWo,
                                                       const float* __restrict__ tbo,
                                                       const float* __restrict__ lng,
                                                       const float* __restrict__ lnb)
{
    const int y = blockIdx.y;
    const int part = y >> 3;
    const int b = y & 7;
    const int T = part ? NT2 : NT1;
    const int base = part ? (M1R + b*NT2) : (b*NT1);
    if (blockIdx.x * 64 >= T) return;

    extern __shared__ float sm[];
    float* sK   = sm;
    float* sV   = sm + 8192;
    float* sAOt = sm + 16384;
    float* sWs  = sm + 16384 + 128*65;

    const int tid = threadIdx.x;
    const int head = tid >> 7;
    const int wt = tid & 127;
    const int lane = wt & 31, warp4 = wt >> 5;
    const int qi = blockIdx.x*64 + warp4*16 + (lane & 15);
    const int half = lane >> 4;

    float4 qreg[16];
    if (qi < T) {
        const float* qp = g_Q + ((size_t)base + qi)*128 + head*64;
        #pragma unroll
        for (int i=0;i<16;i++) qreg[i] = *(const float4*)(qp + i*4);
    } else {
        #pragma unroll
        for (int i=0;i<16;i++) qreg[i] = make_float4(0.f,0.f,0.f,0.f);
    }
    float m = -1e30f, l = 0.f;
    float o[64];
    #pragma unroll
    for (int d=0;d<64;d++) o[d]=0.f;

    const int half0 = (T + 1) >> 1;
    const int kbase = half ? half0 : 0;
    const int kend  = half ? T : half0;
    const int hl1 = T - half0;
    const int nch = (((half0 > hl1) ? half0 : hl1) + 31) >> 5;

    for (int c=0;c<nch;c++) {
        __syncthreads();
        #pragma unroll
        for (int u=0;u<16;u++) {
            int e = (tid*16 + u)*4;
            int hd = e >> 13;
            int r  = e & 8191;
            int isV = r >> 12;
            int e3 = r & 4095;
            int hh = e3 >> 11, kk = (e3 >> 6) & 31, d = e3 & 63;
            int kglob = (hh ? half0 : 0) + c*32 + kk;
            int lim = hh ? T : half0;
            float4 v = make_float4(0.f,0.f,0.f,0.f);
            if (kglob < lim) {
                const float* src = (isV ? g_V : g_K) + ((size_t)base + kglob)*128 + hd*64 + d;
                v = *(const float4*)src;
            }
            float* dst = (isV ? sV : sK) + hd*4096 + e3;
            *(float4*)dst = v;
        }
        __syncthreads();
        const int k0 = kbase + c*32;
        const float* sKh = sK + head*4096 + half*2048;
        const float* sVh = sV + head*4096 + half*2048;
        for (int kk=0;kk<32;kk++) {
            const float4* kr = (const float4*)(sKh + kk*64);
            float4 a4 = make_float4(0.f,0.f,0.f,0.f);
            #pragma unroll
            for (int i=0;i<16;i++) {
                float4 kv = kr[i];
                a4.x = fmaf(kv.x, qreg[i].x, a4.x);
                a4.y = fmaf(kv.y, qreg[i].y, a4.y);
                a4.z = fmaf(kv.z, qreg[i].z, a4.z);
                a4.w = fmaf(kv.w, qreg[i].w, a4.w);
            }
            float s = ((a4.x+a4.y)+(a4.z+a4.w))*0.125f;
            if (k0 + kk < kend) {
                if (s > m) {
                    float f = fexp(m - s);
                    l *= f;
                    #pragma unroll
                    for (int d=0;d<64;d++) o[d]*=f;
                    m = s;
                }
                float e = fexp(s - m);
                l += e;
                const float4* vr = (const float4*)(sVh + kk*64);
                #pragma unroll
                for (int i=0;i<16;i++) {
                    float4 vv = vr[i];
                    o[i*4+0] = fmaf(e, vv.x, o[i*4+0]);
                    o[i*4+1] = fmaf(e, vv.y, o[i*4+1]);
                    o[i*4+2] = fmaf(e, vv.z, o[i*4+2]);
                    o[i*4+3] = fmaf(e, vv.w, o[i*4+3]);
                }
            }
        }
    }
    float m2 = __shfl_xor_sync(0xffffffffu, m, 16);
    float Mx = fmaxf(m, m2);
    float f1 = fexp(m - Mx), f2 = fexp(m2 - Mx);
    float l2 = __shfl_xor_sync(0xffffffffu, l, 16);
    l = l*f1 + l2*f2;
    #pragma unroll
    for (int d=0;d<64;d++) {
        float o2 = __shfl_xor_sync(0xffffffffu, o[d], 16);
        o[d] = o[d]*f1 + o2*f2;
    }
    __syncthreads();
    if (half == 0) {
        float inv = 1.0f / l;
        int qlocal = warp4*16 + (lane & 15);
        #pragma unroll
        for (int d=0;d<64;d++)
            sAOt[(head*64 + d)*65 + qlocal] = o[d]*inv;
    }
    __syncthreads();

    const int tn = tid & 31, tm = tid >> 5;
    float acc[8][4];
    #pragma unroll
    for (int i=0;i<8;i++)
        #pragma unroll
        for (int j=0;j<4;j++) acc[i][j] = 0.f;

    for (int kk = 0; kk < 128; kk += 16) {
        int e0 = tid*8, e1 = tid*8 + 4;
        float4 w0 = *(const float4*)(tWo + (size_t)(kk + (e0>>7))*128 + (e0&127));
        float4 w1 = *(const float4*)(tWo + (size_t)(kk + (e1>>7))*128 + (e1&127));
        __syncthreads();
        *(float4*)&sWs[e0] = w0;
        *(float4*)&sWs[e1] = w1;
        __syncthreads();
        #pragma unroll
        for (int k=0;k<16;k++) {
            float bv[4];
            *(float4*)bv = *(const float4*)&sWs[k*128 + tn*4];
            const float* ar = &sAOt[(kk+k)*65 + tm*8];
            #pragma unroll
            for (int i=0;i<8;i++) {
                float a = ar[i];
                #pragma unroll
                for (int j=0;j<4;j++) acc[i][j] = fmaf(a, bv[j], acc[i][j]);
            }
        }
    }

    float4 bo4 = *(const float4*)(tbo + tn*4);
    float bo[4] = {bo4.x, bo4.y, bo4.z, bo4.w};
    float4 g4 = *(const float4*)(lng + tn*4);
    float4 be4 = *(const float4*)(lnb + tn*4);
    float gg[4] = {g4.x, g4.y, g4.z, g4.w};
    float lb[4] = {be4.x, be4.y, be4.z, be4.w};

    #pragma unroll
    for (int i=0;i<8;i++) {
        int qrow = blockIdx.x*64 + tm*8 + i;
        if (qrow >= T) continue;
        size_t gr = (size_t)base + qrow;
        float4 rv = *(const float4*)(g_X + gr*128 + tn*4);
        float v[4];
        v[0] = acc[i][0] + bo[0] + rv.x;
        v[1] = acc[i][1] + bo[1] + rv.y;
        v[2] = acc[i][2] + bo[2] + rv.z;
        v[3] = acc[i][3] + bo[3] + rv.w;
        float s = v[0]+v[1]+v[2]+v[3];
        float s2 = v[0]*v[0]+v[1]*v[1]+v[2]*v[2]+v[3]*v[3];
        #pragma unroll
        for (int off=16; off>0; off>>=1) {
            s  += __shfl_xor_sync(0xffffffffu, s,  off);
            s2 += __shfl_xor_sync(0xffffffffu, s2, off);
        }
        float mean = s * (1.f/128.f);
        float var  = s2 * (1.f/128.f) - mean*mean;
        float rs   = rsqrtf(var + 1e-5f);
        float4 ov;
        ov.x = (v[0]-mean)*rs*gg[0] + lb[0];
        ov.y = (v[1]-mean)*rs*gg[1] + lb[1];
        ov.z = (v[2]-mean)*rs*gg[2] + lb[2];
        ov.w = (v[3]-mean)*rs*gg[3] + lb[3];
        *(float4*)(g_X2 + gr*128 + tn*4) = ov;
    }
}

// ---------------- FUSED FFN (tf32 mma): relu(X2@W1+b1)@W2+b2 + res + LN2 ----------------
// dyn smem: As 32*36 | Ws 32*132 | F 32*132
__global__ void __launch_bounds__(256, 1) ffn_kernel(
    const float* __restrict__ fW1, const float* __restrict__ fb1,
    const float* __restrict__ fW2, const float* __restrict__ fb2,
    const float* __restrict__ lng, const float* __restrict__ lnb,
    float* __restrict__ dlast)
{
    extern __shared__ float sm[];
    float* As = sm;                    // 32*36
    float* Ws = sm + 32*36;            // 32*132
    float* F  = sm + 32*36 + 32*132;   // 32*132

    const int m0 = blockIdx.x * 32;
    const int tid = threadIdx.x;
    const int lane = tid & 31, warp = tid >> 5;
    const int g = lane >> 2, tig = lane & 3;
    const int n0w = warp * 16;

    float acc[2][2][4];
    #pragma unroll
    for (int a=0;a<2;a++)
        #pragma unroll
        for (int b=0;b<2;b++)
            #pragma unroll
            for (int c=0;c<4;c++) acc[a][b][c] = 0.f;

    const int ar = (tid*4) >> 5;
    const int ac = (tid*4) & 31;
    const int grow = m0 + ar;

    // phase 1: F = relu(X2 @ W1 + b1)  (tf32 in smem)
    for (int kc = 0; kc < 128; kc += 32) {
        __syncthreads();
        {
            float4 a4 = make_float4(0.f,0.f,0.f,0.f);
            if (grow < MTR) a4 = *(const float4*)(g_X2 + (size_t)grow*128 + kc + ac);
            *(float4*)&As[ar*36 + ac] =
                make_float4(f2tf(a4.x), f2tf(a4.y), f2tf(a4.z), f2tf(a4.w));
        }
        stage_W(Ws, fW1, kc, tid);
        __syncthreads();
        mma_chunk(As, Ws, n0w, g, tig, acc);
    }
    __syncthreads();
    #pragma unroll
    for (int ni=0;ni<2;ni++) {
        int col = n0w + ni*8 + tig*2;
        float b0 = fb1[col], b1v = fb1[col+1];
        #pragma unroll
        for (int mi=0;mi<2;mi++) {
            int row = mi*16 + g;
            F[row*132 + col]       = f2tf(fmaxf(acc[mi][ni][0]+b0,  0.f));
            F[row*132 + col+1]     = f2tf(fmaxf(acc[mi][ni][1]+b1v, 0.f));
            F[(row+8)*132 + col]   = f2tf(fmaxf(acc[mi][ni][2]+b0,  0.f));
            F[(row+8)*132 + col+1] = f2tf(fmaxf(acc[mi][ni][3]+b1v, 0.f));
        }
    }

    // phase 2: out = F @ W2
    #pragma unroll
    for (int a=0;a<2;a++)
        #pragma unroll
        for (int b=0;b<2;b++)
            #pragma unroll
            for (int c=0;c<4;c++) acc[a][b][c] = 0.f;

    for (int kc = 0; kc < 128; kc += 32) {
        __syncthreads();
        stage_W(Ws, fW2, kc, tid);
        __syncthreads();
        mma_chunk_F(F, kc, Ws, n0w, g, tig, acc);
    }

    // stash phase-2 result (+b2) into F (fp32 raw)
    __syncthreads();
    #pragma unroll
    for (int ni=0;ni<2;ni++) {
        int col = n0w + ni*8 + tig*2;
        float b0 = fb2[col], b1v = fb2[col+1];
        #pragma unroll
        for (int mi=0;mi<2;mi++) {
            int row = mi*16 + g;
            F[row*132 + col]       = acc[mi][ni][0]+b0;
            F[row*132 + col+1]     = acc[mi][ni][1]+b1v;
            F[(row+8)*132 + col]   = acc[mi][ni][2]+b0;
            F[(row+8)*132 + col+1] = acc[mi][ni][3]+b1v;
        }
    }
    __syncthreads();

    // LN pass: warp w handles rows w*4 .. w*4+3
    float4 g4 = *(const float4*)(lng + lane*4);
    float4 be4 = *(const float4*)(lnb + lane*4);
    #pragma unroll
    for (int i=0;i<4;i++) {
        int row = warp*4 + i;
        int r = m0 + row;
        if (r >= MTR) continue;
        float4 fv = *(const float4*)&F[row*132 + lane*4];
        float4 rv = *(const float4*)(g_X2 + (size_t)r*128 + lane*4);
        float v[4] = {fv.x+rv.x, fv.y+rv.y, fv.z+rv.z, fv.w+rv.w};
        float s = v[0]+v[1]+v[2]+v[3];
        float s2 = v[0]*v[0]+v[1]*v[1]+v[2]*v[2]+v[3]*v[3];
        #pragma unroll
        for (int off=16; off>0; off>>=1) {
            s  += __shfl_xor_sync(0xffffffffu, s,  off);
            s2 += __shfl_xor_sync(0xffffffffu, s2, off);
        }
        float mean = s * (1.f/128.f);
        float var  = s2 * (1.f/128.f) - mean*mean;
        float rs   = rsqrtf(var + 1e-5f);
        float4 ov;
        ov.x = (v[0]-mean)*rs*g4.x + be4.x;
        ov.y = (v[1]-mean)*rs*g4.y + be4.y;
        ov.z = (v[2]-mean)*rs*g4.z + be4.z;
        ov.w = (v[3]-mean)*rs*g4.w + be4.w;
        if (r < M1R) {
            *(float4*)(g_hout + (size_t)r*128 + lane*4) = ov;
        } else {
            int rr = r - M1R;
            int t  = rr % NT2;
            if (t == 0) continue;
            int b  = rr / NT2;
            *(float4*)(dlast + ((size_t)b*NL + t - 1)*128 + lane*4) = ov;
        }
    }
}

// ---------------- cls pooling ----------------
__global__ void pool_kernel(const float* __restrict__ pW,
                            const float* __restrict__ pb, float* __restrict__ dout)
{
    int b = blockIdx.x, j = threadIdx.x;
    __shared__ float s[128];
    s[j] = g_hout[((size_t)b*NT1)*128 + j];
    __syncthreads();
    float acc = pb[j];
    #pragma unroll
    for (int k=0;k<128;k++) acc = fmaf(s[k], pW[k*128 + j], acc);
    dout[b*128 + j] = tanhf(acc);
}

// ---------------- launch ----------------
extern "C" void kernel_launch(void* const* d_in, const int* in_sizes, int n_in,
                              void* d_out, int out_size)
{
    (void)in_sizes; (void)n_in; (void)out_size;
    const float* x       = (const float*)d_in[0];
    const float* ts      = (const float*)d_in[1];
    const float* w_per   = (const float*)d_in[2];
    const float* b_per   = (const float*)d_in[3];
    const float* w_lin   = (const float*)d_in[4];
    const float* b_lin   = (const float*)d_in[5];
    const float* Wq_t    = (const float*)d_in[6];
    const float* bq_t    = (const float*)d_in[7];
    const float* Wk_t    = (const float*)d_in[8];
    const float* bk_t    = (const float*)d_in[9];
    const float* Wo_t    = (const float*)d_in[10];
    const float* bo_t    = (const float*)d_in[11];
    const float* pos_emb = (const float*)d_in[12];
    const float* cls_emb = (const float*)d_in[13];
    const float* tWq = (const float*)d_in[14];
    const float* tbq = (const float*)d_in[15];
    const float* tWk = (const float*)d_in[16];
    const float* tbk = (const float*)d_in[17];
    const float* tWv = (const float*)d_in[18];
    const float* tbv = (const float*)d_in[19];
    const float* tWo = (const float*)d_in[20];
    const float* tbo = (const float*)d_in[21];
    const float* ln1_g = (const float*)d_in[22];
    const float* ln1_b = (const float*)d_in[23];
    const float* fW1 = (const float*)d_in[24];
    const float* fb1 = (const float*)d_in[25];
    const float* fW2 = (const float*)d_in[26];
    const float* fb2 = (const float*)d_in[27];
    const float* ln2_g = (const float*)d_in[28];
    const float* ln2_b = (const float*)d_in[29];
    const float* pW  = (const float*)d_in[30];
    const float* pb  = (const float*)d_in[31];
    float* dout = (float*)d_out;

    float *Qb, *Kb, *Qc, *o32a, *o32c;
    cudaGetSymbolAddress((void**)&Qb,   g_Qb);
    cudaGetSymbolAddress((void**)&Kb,   g_Kb);
    cudaGetSymbolAddress((void**)&Qc,   g_Qc);
    cudaGetSymbolAddress((void**)&o32a, g_o32a);
    cudaGetSymbolAddress((void**)&o32c, g_o32c);

    const int TATTN_SMEM = (8192 + 8192 + 128*65 + 2048) * 4;
    cudaFuncSetAttribute(tattn_kernel, cudaFuncAttributeMaxDynamicSharedMemorySize, TATTN_SMEM);
    const int FFN_SMEM = (32*36 + 32*132 + 32*132) * 4;   // 38400 B

    // 1. K/Q projections with inline time-embedding (tf32 mma)
    kq_gemm_kernel<<<dim3(128, 1, 3), 256>>>(ts, w_per, b_per, w_lin, b_lin,
                                             Wq_t, bq_t, Wk_t, bk_t);

    // 2. masked channel attention (main + cls)
    mta_kernel<<<dim3(10, NB*2), 128>>>(Qb, Qc, Kb, x, o32a, o32c);

    // 3. build merged tblock input (incl. cls rows)
    proj32_kernel<<<321, 256>>>(o32a, o32c, Wo_t, bo_t, pos_emb, cls_emb);

    // 4. QKV (tf32 mma)
    qkv_gemm_kernel<<<dim3((MTR+31)/32, 1, 3), 256>>>(tWq, tbq, tWk, tbk, tWv, tbv);

    // 5. fused attention + Wo + residual + LN1 → X2
    tattn_kernel<<<dim3((NT2+63)/64, 16), 256, TATTN_SMEM>>>(tWo, tbo, ln1_g, ln1_b);

    // 6. fused FFN (tf32 mma) + residual + LN2 → hout / last_hidden
    ffn_kernel<<<(MTR+31)/32, 256, FFN_SMEM>>>(fW1, fb1, fW2, fb2, ln2_g, ln2_b, dout + 1024);

    // 7. cls pooling
    pool_kernel<<<NB, 128>>>(pW, pb, dout);
}